// round 1
// baseline (speedup 1.0000x reference)
#include <cuda_runtime.h>
#include <math.h>

// ---------------- problem constants ----------------
#define B_    2
#define S_    2048
#define H_    2048
#define NH_   16
#define QLORA 1536
#define KVLORA 512
#define DNOPE 128
#define DROPE 64
#define DV_   128
#define DQK   192          // 128 + 64
#define M_    (B_ * S_)    // 4096 rows (b,s) flattened

// ---------------- device scratch (static; no allocations allowed) ----------------
__device__ float g_qa  [(size_t)M_ * QLORA];             // 25 MB
__device__ float g_q   [(size_t)M_ * (NH_ * DQK)];       // 50 MB (4096 x 3072)
__device__ float g_kv  [(size_t)M_ * (KVLORA + DROPE)];  // 9.4 MB (4096 x 576)
__device__ float g_kvc [(size_t)M_ * KVLORA];            // 8.4 MB
__device__ float g_kpe [(size_t)M_ * DROPE];             // 1 MB
__device__ float g_kvx [(size_t)M_ * (NH_ * (DNOPE + DV_))]; // 67 MB (4096 x 4096)
__device__ float g_kf  [(size_t)M_ * (NH_ * DQK)];       // 50 MB (4096 x 3072)
__device__ float g_sc  [(size_t)B_ * NH_ * S_ * S_];     // 536 MB (32 x 2048 x 2048)
__device__ float g_ao  [(size_t)M_ * (NH_ * DV_)];       // 33.5 MB (4096 x 2048)
__device__ float g_cos [S_ * (DROPE / 2)];
__device__ float g_sin [S_ * (DROPE / 2)];

// ---------------- generic strided-batched SGEMM ----------------
// C[m,n] = alpha * sum_k A[m,k] * B(k,n),  B(k,n) = TRANSB ? B[n*ldb+k] : B[k*ldb+n]
// batch z: b = z/nh, h = z%nh; operand base += b*s?b + h*s?h
template<bool TRANSB>
__global__ void __launch_bounds__(256)
gemm_kernel(const float* __restrict__ A, const float* __restrict__ B,
            float* __restrict__ C,
            int M, int N, int K, int lda, int ldb, int ldc,
            long long sAb, long long sAh, long long sBb, long long sBh,
            long long sCb, long long sCh, int nh, float alpha)
{
    int z  = blockIdx.z;
    int bb = z / nh, hh = z % nh;
    A += (long long)bb * sAb + (long long)hh * sAh;
    B += (long long)bb * sBb + (long long)hh * sBh;
    C += (long long)bb * sCb + (long long)hh * sCh;

    __shared__ float As[8][129];
    __shared__ float Bs[8][129];

    const int tid = threadIdx.x;
    const int tx = tid & 15, ty = tid >> 4;
    const int m0 = blockIdx.y * 128, n0 = blockIdx.x * 128;

    float acc[8][8];
#pragma unroll
    for (int r = 0; r < 8; r++)
#pragma unroll
        for (int c = 0; c < 8; c++) acc[r][c] = 0.f;

    for (int k0 = 0; k0 < K; k0 += 8) {
        // A tile: 128 rows x 8 k (row-major, coalesced 32B per 8 lanes)
#pragma unroll
        for (int i = tid; i < 1024; i += 256) {
            int m = i >> 3, kk = i & 7;
            int gm = m0 + m, gk = k0 + kk;
            float v = 0.f;
            if (gm < M && gk < K) v = A[(long long)gm * lda + gk];
            As[kk][m] = v;
        }
        // B tile
#pragma unroll
        for (int i = tid; i < 1024; i += 256) {
            float v = 0.f;
            int n, kk;
            if (TRANSB) {
                n = i >> 3; kk = i & 7;
                int gn = n0 + n, gk = k0 + kk;
                if (gn < N && gk < K) v = B[(long long)gn * ldb + gk];
            } else {
                kk = i >> 7; n = i & 127;
                int gn = n0 + n, gk = k0 + kk;
                if (gn < N && gk < K) v = B[(long long)gk * ldb + gn];
            }
            Bs[kk][n] = v;
        }
        __syncthreads();
#pragma unroll
        for (int kk = 0; kk < 8; kk++) {
            float a[8], b[8];
#pragma unroll
            for (int r = 0; r < 8; r++) a[r] = As[kk][ty + 16 * r];
#pragma unroll
            for (int c = 0; c < 8; c++) b[c] = Bs[kk][tx + 16 * c];
#pragma unroll
            for (int r = 0; r < 8; r++)
#pragma unroll
                for (int c = 0; c < 8; c++) acc[r][c] += a[r] * b[c];
        }
        __syncthreads();
    }

#pragma unroll
    for (int r = 0; r < 8; r++) {
        int gm = m0 + ty + 16 * r;
        if (gm >= M) continue;
#pragma unroll
        for (int c = 0; c < 8; c++) {
            int gn = n0 + tx + 16 * c;
            if (gn < N) C[(long long)gm * ldc + gn] = alpha * acc[r][c];
        }
    }
}

// ---------------- RMSNorm (one block per row) ----------------
__global__ void __launch_bounds__(256)
rmsnorm_kernel(const float* __restrict__ x, int ldx,
               const float* __restrict__ w,
               float* __restrict__ y, int ldy, int cols)
{
    const int row = blockIdx.x;
    const float* xr = x + (long long)row * ldx;
    float* yr = y + (long long)row * ldy;
    float ss = 0.f;
    for (int c = threadIdx.x; c < cols; c += 256) { float v = xr[c]; ss += v * v; }
    __shared__ float red[256];
    red[threadIdx.x] = ss;
    __syncthreads();
    for (int s = 128; s > 0; s >>= 1) {
        if (threadIdx.x < s) red[threadIdx.x] += red[threadIdx.x + s];
        __syncthreads();
    }
    float inv = 1.f / sqrtf(red[0] / (float)cols + 1e-6f);
    for (int c = threadIdx.x; c < cols; c += 256) yr[c] = w[c] * xr[c] * inv;
}

// ---------------- RoPE freq table ----------------
__global__ void freqs_kernel(float* __restrict__ cosd, float* __restrict__ sind)
{
    int t = blockIdx.x, i = threadIdx.x;  // i in [0,32)
    double inv = pow(10000.0, -(double)(2 * i) / (double)DROPE);
    double f = (double)t * inv;
    cosd[t * 32 + i] = (float)cos(f);
    sind[t * 32 + i] = (float)sin(f);
}

// RoPE on q_pe (in place in g_q): grid M_, 512 threads = 16 heads x 32 pairs
__global__ void __launch_bounds__(512)
rope_q_kernel(float* __restrict__ q, const float* __restrict__ cosd,
              const float* __restrict__ sind)
{
    int m = blockIdx.x;
    int t = m & (S_ - 1);
    int h = threadIdx.x >> 5, i = threadIdx.x & 31;
    float cs = cosd[t * 32 + i], sn = sind[t * 32 + i];
    long long base = (long long)m * (NH_ * DQK) + h * DQK + DNOPE + 2 * i;
    float e = q[base], o = q[base + 1];
    q[base]     = e * cs - o * sn;
    q[base + 1] = e * sn + o * cs;
}

// RoPE on k_pe: read from g_kv cols [512,576), write g_kpe
__global__ void rope_k_kernel(const float* __restrict__ kv, float* __restrict__ kpe,
                              const float* __restrict__ cosd, const float* __restrict__ sind)
{
    int m = blockIdx.x;
    int t = m & (S_ - 1);
    int i = threadIdx.x;  // 32 pairs
    float cs = cosd[t * 32 + i], sn = sind[t * 32 + i];
    long long base = (long long)m * (KVLORA + DROPE) + KVLORA + 2 * i;
    float e = kv[base], o = kv[base + 1];
    kpe[m * DROPE + 2 * i]     = e * cs - o * sn;
    kpe[m * DROPE + 2 * i + 1] = e * sn + o * cs;
}

// Assemble kf[m, h*192+d] = d<128 ? kvx[m, h*256+d] : kpe[m, d-128]
__global__ void build_kf_kernel(const float* __restrict__ kvx, const float* __restrict__ kpe,
                                float* __restrict__ kf)
{
    long long idx = (long long)blockIdx.x * 256 + threadIdx.x;  // < M_*3072
    int col = (int)(idx % (NH_ * DQK));
    long long m = idx / (NH_ * DQK);
    int h = col / DQK, d = col % DQK;
    float v;
    if (d < DNOPE) v = kvx[m * (NH_ * (DNOPE + DV_)) + h * (DNOPE + DV_) + d];
    else           v = kpe[m * DROPE + (d - DNOPE)];
    kf[idx] = v;
}

// Row softmax over S_ keys. grid (S_, B_*NH_), 256 threads.
__global__ void __launch_bounds__(256)
softmax_kernel(float* __restrict__ s)
{
    float* row = s + ((long long)blockIdx.y * S_ + blockIdx.x) * (long long)S_;
    __shared__ float red[256];
    float mx = -1e30f;
    for (int c = threadIdx.x; c < S_; c += 256) mx = fmaxf(mx, row[c]);
    red[threadIdx.x] = mx;
    __syncthreads();
    for (int st = 128; st > 0; st >>= 1) {
        if (threadIdx.x < st) red[threadIdx.x] = fmaxf(red[threadIdx.x], red[threadIdx.x + st]);
        __syncthreads();
    }
    mx = red[0];
    __syncthreads();
    float sum = 0.f;
    for (int c = threadIdx.x; c < S_; c += 256) {
        float e = __expf(row[c] - mx);
        row[c] = e;
        sum += e;
    }
    red[threadIdx.x] = sum;
    __syncthreads();
    for (int st = 128; st > 0; st >>= 1) {
        if (threadIdx.x < st) red[threadIdx.x] += red[threadIdx.x + st];
        __syncthreads();
    }
    float inv = 1.f / red[0];
    for (int c = threadIdx.x; c < S_; c += 256) row[c] *= inv;
}

// ---------------- launch ----------------
extern "C" void kernel_launch(void* const* d_in, const int* in_sizes, int n_in,
                              void* d_out, int out_size)
{
    const float* hs        = (const float*)d_in[0];
    const float* wq_a      = (const float*)d_in[1];
    const float* q_norm_w  = (const float*)d_in[2];
    const float* wq_b      = (const float*)d_in[3];
    const float* wkv_a     = (const float*)d_in[4];
    const float* kv_norm_w = (const float*)d_in[5];
    const float* wkv_b     = (const float*)d_in[6];
    const float* wo        = (const float*)d_in[7];
    float* out = (float*)d_out;

    float *p_qa, *p_q, *p_kv, *p_kvc, *p_kpe, *p_kvx, *p_kf, *p_sc, *p_ao, *p_cos, *p_sin;
    cudaGetSymbolAddress((void**)&p_qa,  g_qa);
    cudaGetSymbolAddress((void**)&p_q,   g_q);
    cudaGetSymbolAddress((void**)&p_kv,  g_kv);
    cudaGetSymbolAddress((void**)&p_kvc, g_kvc);
    cudaGetSymbolAddress((void**)&p_kpe, g_kpe);
    cudaGetSymbolAddress((void**)&p_kvx, g_kvx);
    cudaGetSymbolAddress((void**)&p_kf,  g_kf);
    cudaGetSymbolAddress((void**)&p_sc,  g_sc);
    cudaGetSymbolAddress((void**)&p_ao,  g_ao);
    cudaGetSymbolAddress((void**)&p_cos, g_cos);
    cudaGetSymbolAddress((void**)&p_sin, g_sin);

    const float scale = 1.0f / sqrtf((float)DQK);

    // freq table (cheap, recomputed every launch for graph determinism)
    freqs_kernel<<<S_, 32>>>(p_cos, p_sin);

    // q_a = hs @ wq_a^T       [4096 x 1536], K=2048
    gemm_kernel<true><<<dim3(QLORA / 128, M_ / 128, 1), 256>>>(
        hs, wq_a, p_qa, M_, QLORA, H_, H_, H_, QLORA,
        0, 0, 0, 0, 0, 0, 1, 1.f);

    // rmsnorm(q_a) in place
    rmsnorm_kernel<<<M_, 256>>>(p_qa, QLORA, q_norm_w, p_qa, QLORA, QLORA);

    // q = q_a @ wq_b^T        [4096 x 3072], K=1536
    gemm_kernel<true><<<dim3((NH_ * DQK) / 128, M_ / 128, 1), 256>>>(
        p_qa, wq_b, p_q, M_, NH_ * DQK, QLORA, QLORA, QLORA, NH_ * DQK,
        0, 0, 0, 0, 0, 0, 1, 1.f);

    // kv = hs @ wkv_a^T       [4096 x 576], K=2048
    gemm_kernel<true><<<dim3((KVLORA + DROPE + 127) / 128, M_ / 128, 1), 256>>>(
        hs, wkv_a, p_kv, M_, KVLORA + DROPE, H_, H_, H_, KVLORA + DROPE,
        0, 0, 0, 0, 0, 0, 1, 1.f);

    // kv_c = rmsnorm(kv[:, :512])
    rmsnorm_kernel<<<M_, 256>>>(p_kv, KVLORA + DROPE, kv_norm_w, p_kvc, KVLORA, KVLORA);

    // k_pe = rope(kv[:, 512:576])
    rope_k_kernel<<<M_, 32>>>(p_kv, p_kpe, p_cos, p_sin);

    // kv_x = kv_c @ wkv_b^T   [4096 x 4096], K=512
    gemm_kernel<true><<<dim3((NH_ * (DNOPE + DV_)) / 128, M_ / 128, 1), 256>>>(
        p_kvc, wkv_b, p_kvx, M_, NH_ * (DNOPE + DV_), KVLORA, KVLORA, KVLORA,
        NH_ * (DNOPE + DV_), 0, 0, 0, 0, 0, 0, 1, 1.f);

    // rope q_pe in place
    rope_q_kernel<<<M_, 512>>>(p_q, p_cos, p_sin);

    // assemble kf [4096 x (16*192)]
    build_kf_kernel<<<(int)(((long long)M_ * NH_ * DQK) / 256), 256>>>(p_kvx, p_kpe, p_kf);

    // scores[z] = scale * Q_z @ Kf_z^T,  z = b*16+h, [2048 x 2048], K=192
    gemm_kernel<true><<<dim3(S_ / 128, S_ / 128, B_ * NH_), 256>>>(
        p_q, p_kf, p_sc, S_, S_, DQK,
        NH_ * DQK, NH_ * DQK, S_,
        (long long)S_ * NH_ * DQK, (long long)DQK,       // A strides (b, h)
        (long long)S_ * NH_ * DQK, (long long)DQK,       // B strides
        (long long)NH_ * S_ * S_,  (long long)S_ * S_,   // C strides
        NH_, scale);

    // softmax over keys
    softmax_kernel<<<dim3(S_, B_ * NH_), 256>>>(p_sc);

    // ao[z] = attn_z @ V_z   [2048 x 128], K=2048 ; V = kvx[:, h*256+128 : +128]
    gemm_kernel<false><<<dim3(1, S_ / 128, B_ * NH_), 256>>>(
        p_sc, p_kvx + DNOPE, p_ao, S_, DV_, S_,
        S_, NH_ * (DNOPE + DV_), NH_ * DV_,
        (long long)NH_ * S_ * S_, (long long)S_ * S_,                    // A strides
        (long long)S_ * NH_ * (DNOPE + DV_), (long long)(DNOPE + DV_),   // B strides
        (long long)S_ * NH_ * DV_, (long long)DV_,                       // C strides
        NH_, 1.f);

    // out = ao @ wo^T  [4096 x 2048], K=2048
    gemm_kernel<true><<<dim3(H_ / 128, M_ / 128, 1), 256>>>(
        p_ao, wo, out, M_, H_, NH_ * DV_, NH_ * DV_, NH_ * DV_, H_,
        0, 0, 0, 0, 0, 0, 1, 1.f);
}

// round 2
// speedup vs baseline: 1.7253x; 1.7253x over previous
#include <cuda_runtime.h>
#include <cuda_bf16.h>
#include <math.h>
#include <stdint.h>

// ---------------- problem constants ----------------
#define B_    2
#define S_    2048
#define H_    2048
#define NH_   16
#define QLORA 1536
#define KVLORA 512
#define DNOPE 128
#define DROPE 64
#define DV_   128
#define DQK   192
#define M_    (B_ * S_)    // 4096

// ---------------- fp32 scratch ----------------
__device__ float g_qa  [(size_t)M_ * QLORA];
__device__ float g_q   [(size_t)M_ * (NH_ * DQK)];
__device__ float g_kv  [(size_t)M_ * (KVLORA + DROPE)];
__device__ float g_kpe [(size_t)M_ * DROPE];
__device__ float g_kvx [(size_t)M_ * (NH_ * (DNOPE + DV_))];
__device__ float g_sc  [(size_t)B_ * NH_ * S_ * S_];       // 536 MB
__device__ float g_ao  [(size_t)M_ * (NH_ * DV_)];
__device__ float g_cos [S_ * (DROPE / 2)];
__device__ float g_sin [S_ * (DROPE / 2)];

// ---------------- bf16 split (hi/lo) operand buffers ----------------
__device__ __nv_bfloat16 g_hs_h [(size_t)M_ * H_],            g_hs_l [(size_t)M_ * H_];
__device__ __nv_bfloat16 g_wqa_h[(size_t)QLORA * H_],         g_wqa_l[(size_t)QLORA * H_];
__device__ __nv_bfloat16 g_wqb_h[(size_t)NH_ * DQK * QLORA],  g_wqb_l[(size_t)NH_ * DQK * QLORA];
__device__ __nv_bfloat16 g_wkva_h[(size_t)(KVLORA + DROPE) * H_], g_wkva_l[(size_t)(KVLORA + DROPE) * H_];
__device__ __nv_bfloat16 g_wkvb_h[(size_t)NH_ * (DNOPE + DV_) * KVLORA], g_wkvb_l[(size_t)NH_ * (DNOPE + DV_) * KVLORA];
__device__ __nv_bfloat16 g_wo_h [(size_t)H_ * NH_ * DV_],     g_wo_l [(size_t)H_ * NH_ * DV_];
__device__ __nv_bfloat16 g_qa_h [(size_t)M_ * QLORA],         g_qa_l [(size_t)M_ * QLORA];
__device__ __nv_bfloat16 g_qh   [(size_t)M_ * NH_ * DQK],     g_ql   [(size_t)M_ * NH_ * DQK];
__device__ __nv_bfloat16 g_kvc_h[(size_t)M_ * KVLORA],        g_kvc_l[(size_t)M_ * KVLORA];
__device__ __nv_bfloat16 g_kf_h [(size_t)M_ * NH_ * DQK],     g_kf_l [(size_t)M_ * NH_ * DQK];
__device__ __nv_bfloat16 g_v_h  [(size_t)M_ * NH_ * DV_],     g_v_l  [(size_t)M_ * NH_ * DV_];
__device__ __nv_bfloat16 g_at_h [(size_t)B_ * NH_ * S_ * S_], g_at_l [(size_t)B_ * NH_ * S_ * S_];  // 268 MB each
__device__ __nv_bfloat16 g_ao_h [(size_t)M_ * NH_ * DV_],     g_ao_l [(size_t)M_ * NH_ * DV_];

// ---------------- helpers ----------------
__device__ __forceinline__ void split_write(float v, __nv_bfloat16* ph, __nv_bfloat16* pl) {
    __nv_bfloat16 h = __float2bfloat16(v);
    *ph = h;
    *pl = __float2bfloat16(v - __bfloat162float(h));
}

__device__ __forceinline__ void mma_bf16(float* c, const uint32_t* a, const uint32_t* b) {
    asm volatile(
        "mma.sync.aligned.m16n8k16.row.col.f32.bf16.bf16.f32 "
        "{%0,%1,%2,%3}, {%4,%5,%6,%7}, {%8,%9}, {%0,%1,%2,%3};\n"
        : "+f"(c[0]), "+f"(c[1]), "+f"(c[2]), "+f"(c[3])
        : "r"(a[0]), "r"(a[1]), "r"(a[2]), "r"(a[3]), "r"(b[0]), "r"(b[1]));
}

// ---------------- split-3 bf16 tensor-core GEMM ----------------
// C[m,n] = alpha * sum_k A[m,k]*B(k,n);  B(k,n) = TRANSB ? B[n*ldb+k] : B[k*ldb+n]
// A,B given as (hi,lo) bf16 pairs; computes hi*hi + hi*lo + lo*hi in fp32.
template<bool TRANSB>
__global__ void __launch_bounds__(256)
bgemm_kernel(const __nv_bfloat16* __restrict__ Ah, const __nv_bfloat16* __restrict__ Al,
             const __nv_bfloat16* __restrict__ Bh, const __nv_bfloat16* __restrict__ Bl,
             float* __restrict__ C,
             int M, int N, int K, int lda, int ldb, int ldc,
             long long sAb, long long sAhh, long long sBb, long long sBhh,
             long long sCb, long long sChh, int nh, float alpha)
{
    int z = blockIdx.z;
    int bb = z / nh, hh = z % nh;
    Ah += bb * sAb + hh * sAhh;  Al += bb * sAb + hh * sAhh;
    Bh += bb * sBb + hh * sBhh;  Bl += bb * sBb + hh * sBhh;
    C  += bb * sCb + hh * sChh;

    __shared__ __nv_bfloat16 sA_h[128][40], sA_l[128][40];
    __shared__ __nv_bfloat16 sB_h[128][40], sB_l[128][40];

    const int tid = threadIdx.x;
    const int lane = tid & 31, w = tid >> 5;
    const int wm = (w >> 1) * 32, wn = (w & 1) * 64;
    const int m0 = blockIdx.y * 128, n0 = blockIdx.x * 128;
    const int fr = lane >> 2, fc = (lane & 3) * 2;

    float acc[2][8][4] = {};

    for (int k0 = 0; k0 < K; k0 += 32) {
        // ---- A tile: 128 rows x 32 k ----
#pragma unroll
        for (int j = 0; j < 2; j++) {
            int idx = tid + 256 * j;             // 0..511
            int r = idx >> 2, ch = (idx & 3) * 8;
            long long off = (long long)(m0 + r) * lda + k0 + ch;
            *(uint4*)&sA_h[r][ch] = *(const uint4*)(Ah + off);
            *(uint4*)&sA_l[r][ch] = *(const uint4*)(Al + off);
        }
        // ---- B tile ----
        if (TRANSB) {
#pragma unroll
            for (int j = 0; j < 2; j++) {
                int idx = tid + 256 * j;
                int r = idx >> 2, ch = (idx & 3) * 8;
                int gn = n0 + r;
                uint4 vh = make_uint4(0, 0, 0, 0), vl = make_uint4(0, 0, 0, 0);
                if (gn < N) {
                    long long off = (long long)gn * ldb + k0 + ch;
                    vh = *(const uint4*)(Bh + off);
                    vl = *(const uint4*)(Bl + off);
                }
                *(uint4*)&sB_h[r][ch] = vh;
                *(uint4*)&sB_l[r][ch] = vl;
            }
        } else {
            // B is [k][n]: transpose into smem [n][k]
#pragma unroll
            for (int j = 0; j < 2; j++) {
                int idx = tid + 256 * j;          // 32 k-rows x 16 chunks
                int kk = idx >> 4, ch = (idx & 15) * 8;
                int gn = n0 + ch;
                uint4 vh = make_uint4(0, 0, 0, 0), vl = make_uint4(0, 0, 0, 0);
                if (gn < N) {
                    long long off = (long long)(k0 + kk) * ldb + gn;
                    vh = *(const uint4*)(Bh + off);
                    vl = *(const uint4*)(Bl + off);
                }
                __nv_bfloat16 th[8], tl[8];
                *(uint4*)th = vh;  *(uint4*)tl = vl;
#pragma unroll
                for (int t = 0; t < 8; t++) {
                    sB_h[ch + t][kk] = th[t];
                    sB_l[ch + t][kk] = tl[t];
                }
            }
        }
        __syncthreads();

#pragma unroll
        for (int ks = 0; ks < 2; ks++) {
            int kb = ks * 16;
            uint32_t a_h[2][4], a_l[2][4];
#pragma unroll
            for (int mt = 0; mt < 2; mt++) {
                int row = wm + mt * 16 + fr;
                a_h[mt][0] = *(const uint32_t*)&sA_h[row][kb + fc];
                a_h[mt][1] = *(const uint32_t*)&sA_h[row + 8][kb + fc];
                a_h[mt][2] = *(const uint32_t*)&sA_h[row][kb + fc + 8];
                a_h[mt][3] = *(const uint32_t*)&sA_h[row + 8][kb + fc + 8];
                a_l[mt][0] = *(const uint32_t*)&sA_l[row][kb + fc];
                a_l[mt][1] = *(const uint32_t*)&sA_l[row + 8][kb + fc];
                a_l[mt][2] = *(const uint32_t*)&sA_l[row][kb + fc + 8];
                a_l[mt][3] = *(const uint32_t*)&sA_l[row + 8][kb + fc + 8];
            }
#pragma unroll
            for (int nt = 0; nt < 8; nt++) {
                int col = wn + nt * 8 + fr;
                uint32_t b_h[2], b_l[2];
                b_h[0] = *(const uint32_t*)&sB_h[col][kb + fc];
                b_h[1] = *(const uint32_t*)&sB_h[col][kb + fc + 8];
                b_l[0] = *(const uint32_t*)&sB_l[col][kb + fc];
                b_l[1] = *(const uint32_t*)&sB_l[col][kb + fc + 8];
#pragma unroll
                for (int mt = 0; mt < 2; mt++) {
                    mma_bf16(acc[mt][nt], a_h[mt], b_h);
                    mma_bf16(acc[mt][nt], a_h[mt], b_l);
                    mma_bf16(acc[mt][nt], a_l[mt], b_h);
                }
            }
        }
        __syncthreads();
    }

    // ---- epilogue ----
#pragma unroll
    for (int mt = 0; mt < 2; mt++) {
#pragma unroll
        for (int nt = 0; nt < 8; nt++) {
            int row = m0 + wm + mt * 16 + fr;
            int col = n0 + wn + nt * 8 + fc;
            if (col < N) {
                C[(long long)row * ldc + col]       = alpha * acc[mt][nt][0];
                C[(long long)row * ldc + col + 1]   = alpha * acc[mt][nt][1];
                C[(long long)(row + 8) * ldc + col]     = alpha * acc[mt][nt][2];
                C[(long long)(row + 8) * ldc + col + 1] = alpha * acc[mt][nt][3];
            }
        }
    }
}

// ---------------- fp32 -> (hi,lo) bf16 convert ----------------
__global__ void convert_split_kernel(const float* __restrict__ x,
                                     __nv_bfloat16* __restrict__ h,
                                     __nv_bfloat16* __restrict__ l, long long n)
{
    long long i = (long long)blockIdx.x * 256 + threadIdx.x;
    if (i < n) split_write(x[i], h + i, l + i);
}

// ---------------- RMSNorm -> split bf16 ----------------
__global__ void __launch_bounds__(256)
rmsnorm_split_kernel(const float* __restrict__ x, int ldx, const float* __restrict__ w,
                     __nv_bfloat16* __restrict__ yh, __nv_bfloat16* __restrict__ yl,
                     int ldy, int cols)
{
    const int row = blockIdx.x;
    const float* xr = x + (long long)row * ldx;
    float ss = 0.f;
    for (int c = threadIdx.x; c < cols; c += 256) { float v = xr[c]; ss += v * v; }
    __shared__ float red[256];
    red[threadIdx.x] = ss;
    __syncthreads();
    for (int s = 128; s > 0; s >>= 1) {
        if (threadIdx.x < s) red[threadIdx.x] += red[threadIdx.x + s];
        __syncthreads();
    }
    float inv = 1.f / sqrtf(red[0] / (float)cols + 1e-6f);
    long long base = (long long)row * ldy;
    for (int c = threadIdx.x; c < cols; c += 256)
        split_write(w[c] * xr[c] * inv, yh + base + c, yl + base + c);
}

// ---------------- RoPE ----------------
__global__ void freqs_kernel(float* __restrict__ cosd, float* __restrict__ sind)
{
    int t = blockIdx.x, i = threadIdx.x;
    double inv = pow(10000.0, -(double)(2 * i) / (double)DROPE);
    double f = (double)t * inv;
    cosd[t * 32 + i] = (float)cos(f);
    sind[t * 32 + i] = (float)sin(f);
}

__global__ void __launch_bounds__(512)
rope_q_kernel(float* __restrict__ q, const float* __restrict__ cosd,
              const float* __restrict__ sind)
{
    int m = blockIdx.x;
    int t = m & (S_ - 1);
    int h = threadIdx.x >> 5, i = threadIdx.x & 31;
    float cs = cosd[t * 32 + i], sn = sind[t * 32 + i];
    long long base = (long long)m * (NH_ * DQK) + h * DQK + DNOPE + 2 * i;
    float e = q[base], o = q[base + 1];
    q[base]     = e * cs - o * sn;
    q[base + 1] = e * sn + o * cs;
}

__global__ void rope_k_kernel(const float* __restrict__ kv, float* __restrict__ kpe,
                              const float* __restrict__ cosd, const float* __restrict__ sind)
{
    int m = blockIdx.x;
    int t = m & (S_ - 1);
    int i = threadIdx.x;
    float cs = cosd[t * 32 + i], sn = sind[t * 32 + i];
    long long base = (long long)m * (KVLORA + DROPE) + KVLORA + 2 * i;
    float e = kv[base], o = kv[base + 1];
    kpe[m * DROPE + 2 * i]     = e * cs - o * sn;
    kpe[m * DROPE + 2 * i + 1] = e * sn + o * cs;
}

// ---------------- kf assembly (split bf16) ----------------
__global__ void build_kf_kernel(const float* __restrict__ kvx, const float* __restrict__ kpe,
                                __nv_bfloat16* __restrict__ kfh, __nv_bfloat16* __restrict__ kfl)
{
    long long idx = (long long)blockIdx.x * 256 + threadIdx.x;
    int col = (int)(idx % (NH_ * DQK));
    long long m = idx / (NH_ * DQK);
    int h = col / DQK, d = col % DQK;
    float v;
    if (d < DNOPE) v = kvx[m * (NH_ * (DNOPE + DV_)) + h * (DNOPE + DV_) + d];
    else           v = kpe[m * DROPE + (d - DNOPE)];
    split_write(v, kfh + idx, kfl + idx);
}

// ---------------- V extraction (split bf16, packed [m][h*128+d]) ----------------
__global__ void extract_v_kernel(const float* __restrict__ kvx,
                                 __nv_bfloat16* __restrict__ vh, __nv_bfloat16* __restrict__ vl)
{
    long long idx = (long long)blockIdx.x * 256 + threadIdx.x;   // < M_*2048
    int col = (int)(idx & (NH_ * DV_ - 1));
    long long m = idx >> 11;
    int h = col >> 7, d = col & 127;
    float v = kvx[m * (NH_ * (DNOPE + DV_)) + h * (DNOPE + DV_) + DNOPE + d];
    split_write(v, vh + idx, vl + idx);
}

// ---------------- softmax -> split bf16 ----------------
__global__ void __launch_bounds__(256)
softmax_split_kernel(const float* __restrict__ s,
                     __nv_bfloat16* __restrict__ ah, __nv_bfloat16* __restrict__ al)
{
    long long off = ((long long)blockIdx.y * S_ + blockIdx.x) * (long long)S_;
    const float* row = s + off;
    __shared__ float red[256];
    float mx = -1e30f;
    for (int c = threadIdx.x; c < S_; c += 256) mx = fmaxf(mx, row[c]);
    red[threadIdx.x] = mx;
    __syncthreads();
    for (int st = 128; st > 0; st >>= 1) {
        if (threadIdx.x < st) red[threadIdx.x] = fmaxf(red[threadIdx.x], red[threadIdx.x + st]);
        __syncthreads();
    }
    mx = red[0];
    __syncthreads();
    float sum = 0.f;
    for (int c = threadIdx.x; c < S_; c += 256) sum += __expf(row[c] - mx);
    red[threadIdx.x] = sum;
    __syncthreads();
    for (int st = 128; st > 0; st >>= 1) {
        if (threadIdx.x < st) red[threadIdx.x] += red[threadIdx.x + st];
        __syncthreads();
    }
    float inv = 1.f / red[0];
    for (int c = threadIdx.x; c < S_; c += 256)
        split_write(__expf(row[c] - mx) * inv, ah + off + c, al + off + c);
}

// ---------------- launch ----------------
extern "C" void kernel_launch(void* const* d_in, const int* in_sizes, int n_in,
                              void* d_out, int out_size)
{
    const float* hs        = (const float*)d_in[0];
    const float* wq_a      = (const float*)d_in[1];
    const float* q_norm_w  = (const float*)d_in[2];
    const float* wq_b      = (const float*)d_in[3];
    const float* wkv_a     = (const float*)d_in[4];
    const float* kv_norm_w = (const float*)d_in[5];
    const float* wkv_b     = (const float*)d_in[6];
    const float* wo        = (const float*)d_in[7];
    float* out = (float*)d_out;

    float *p_qa, *p_q, *p_kv, *p_kpe, *p_kvx, *p_sc, *p_ao, *p_cos, *p_sin;
    cudaGetSymbolAddress((void**)&p_qa,  g_qa);
    cudaGetSymbolAddress((void**)&p_q,   g_q);
    cudaGetSymbolAddress((void**)&p_kv,  g_kv);
    cudaGetSymbolAddress((void**)&p_kpe, g_kpe);
    cudaGetSymbolAddress((void**)&p_kvx, g_kvx);
    cudaGetSymbolAddress((void**)&p_sc,  g_sc);
    cudaGetSymbolAddress((void**)&p_ao,  g_ao);
    cudaGetSymbolAddress((void**)&p_cos, g_cos);
    cudaGetSymbolAddress((void**)&p_sin, g_sin);

    __nv_bfloat16 *hs_h, *hs_l, *wqa_h, *wqa_l, *wqb_h, *wqb_l, *wkva_h, *wkva_l;
    __nv_bfloat16 *wkvb_h, *wkvb_l, *wo_h, *wo_l, *qa_h, *qa_l, *q_h, *q_l;
    __nv_bfloat16 *kvc_h, *kvc_l, *kf_h, *kf_l, *v_h, *v_l, *at_h, *at_l, *ao_h, *ao_l;
    cudaGetSymbolAddress((void**)&hs_h,  g_hs_h);   cudaGetSymbolAddress((void**)&hs_l,  g_hs_l);
    cudaGetSymbolAddress((void**)&wqa_h, g_wqa_h);  cudaGetSymbolAddress((void**)&wqa_l, g_wqa_l);
    cudaGetSymbolAddress((void**)&wqb_h, g_wqb_h);  cudaGetSymbolAddress((void**)&wqb_l, g_wqb_l);
    cudaGetSymbolAddress((void**)&wkva_h, g_wkva_h); cudaGetSymbolAddress((void**)&wkva_l, g_wkva_l);
    cudaGetSymbolAddress((void**)&wkvb_h, g_wkvb_h); cudaGetSymbolAddress((void**)&wkvb_l, g_wkvb_l);
    cudaGetSymbolAddress((void**)&wo_h,  g_wo_h);   cudaGetSymbolAddress((void**)&wo_l,  g_wo_l);
    cudaGetSymbolAddress((void**)&qa_h,  g_qa_h);   cudaGetSymbolAddress((void**)&qa_l,  g_qa_l);
    cudaGetSymbolAddress((void**)&q_h,   g_qh);     cudaGetSymbolAddress((void**)&q_l,   g_ql);
    cudaGetSymbolAddress((void**)&kvc_h, g_kvc_h);  cudaGetSymbolAddress((void**)&kvc_l, g_kvc_l);
    cudaGetSymbolAddress((void**)&kf_h,  g_kf_h);   cudaGetSymbolAddress((void**)&kf_l,  g_kf_l);
    cudaGetSymbolAddress((void**)&v_h,   g_v_h);    cudaGetSymbolAddress((void**)&v_l,   g_v_l);
    cudaGetSymbolAddress((void**)&at_h,  g_at_h);   cudaGetSymbolAddress((void**)&at_l,  g_at_l);
    cudaGetSymbolAddress((void**)&ao_h,  g_ao_h);   cudaGetSymbolAddress((void**)&ao_l,  g_ao_l);

    const float scale = 1.0f / sqrtf((float)DQK);
    auto cvblocks = [](long long n) { return (int)((n + 255) / 256); };

    freqs_kernel<<<S_, 32>>>(p_cos, p_sin);

    // input conversions
    convert_split_kernel<<<cvblocks((long long)M_ * H_), 256>>>(hs, hs_h, hs_l, (long long)M_ * H_);
    convert_split_kernel<<<cvblocks((long long)QLORA * H_), 256>>>(wq_a, wqa_h, wqa_l, (long long)QLORA * H_);
    convert_split_kernel<<<cvblocks((long long)NH_ * DQK * QLORA), 256>>>(wq_b, wqb_h, wqb_l, (long long)NH_ * DQK * QLORA);
    convert_split_kernel<<<cvblocks((long long)(KVLORA + DROPE) * H_), 256>>>(wkv_a, wkva_h, wkva_l, (long long)(KVLORA + DROPE) * H_);
    convert_split_kernel<<<cvblocks((long long)NH_ * (DNOPE + DV_) * KVLORA), 256>>>(wkv_b, wkvb_h, wkvb_l, (long long)NH_ * (DNOPE + DV_) * KVLORA);
    convert_split_kernel<<<cvblocks((long long)H_ * NH_ * DV_), 256>>>(wo, wo_h, wo_l, (long long)H_ * NH_ * DV_);

    // q_a = hs @ wq_a^T   [4096 x 1536] K=2048
    bgemm_kernel<true><<<dim3(QLORA / 128, M_ / 128, 1), 256>>>(
        hs_h, hs_l, wqa_h, wqa_l, p_qa, M_, QLORA, H_, H_, H_, QLORA,
        0, 0, 0, 0, 0, 0, 1, 1.f);

    rmsnorm_split_kernel<<<M_, 256>>>(p_qa, QLORA, q_norm_w, qa_h, qa_l, QLORA, QLORA);

    // q = q_a @ wq_b^T    [4096 x 3072] K=1536
    bgemm_kernel<true><<<dim3((NH_ * DQK) / 128, M_ / 128, 1), 256>>>(
        qa_h, qa_l, wqb_h, wqb_l, p_q, M_, NH_ * DQK, QLORA, QLORA, QLORA, NH_ * DQK,
        0, 0, 0, 0, 0, 0, 1, 1.f);

    // kv = hs @ wkv_a^T   [4096 x 576] K=2048
    bgemm_kernel<true><<<dim3((KVLORA + DROPE + 127) / 128, M_ / 128, 1), 256>>>(
        hs_h, hs_l, wkva_h, wkva_l, p_kv, M_, KVLORA + DROPE, H_, H_, H_, KVLORA + DROPE,
        0, 0, 0, 0, 0, 0, 1, 1.f);

    rmsnorm_split_kernel<<<M_, 256>>>(p_kv, KVLORA + DROPE, kv_norm_w, kvc_h, kvc_l, KVLORA, KVLORA);
    rope_k_kernel<<<M_, 32>>>(p_kv, p_kpe, p_cos, p_sin);

    // kv_x = kv_c @ wkv_b^T  [4096 x 4096] K=512
    bgemm_kernel<true><<<dim3((NH_ * (DNOPE + DV_)) / 128, M_ / 128, 1), 256>>>(
        kvc_h, kvc_l, wkvb_h, wkvb_l, p_kvx, M_, NH_ * (DNOPE + DV_), KVLORA, KVLORA, KVLORA,
        NH_ * (DNOPE + DV_), 0, 0, 0, 0, 0, 0, 1, 1.f);

    rope_q_kernel<<<M_, 512>>>(p_q, p_cos, p_sin);
    convert_split_kernel<<<cvblocks((long long)M_ * NH_ * DQK), 256>>>(p_q, q_h, q_l, (long long)M_ * NH_ * DQK);
    build_kf_kernel<<<cvblocks((long long)M_ * NH_ * DQK), 256>>>(p_kvx, p_kpe, kf_h, kf_l);
    extract_v_kernel<<<cvblocks((long long)M_ * NH_ * DV_), 256>>>(p_kvx, v_h, v_l);

    // scores[z] = scale * Q_z @ Kf_z^T   [2048 x 2048] K=192
    bgemm_kernel<true><<<dim3(S_ / 128, S_ / 128, B_ * NH_), 256>>>(
        q_h, q_l, kf_h, kf_l, p_sc, S_, S_, DQK,
        NH_ * DQK, NH_ * DQK, S_,
        (long long)S_ * NH_ * DQK, (long long)DQK,
        (long long)S_ * NH_ * DQK, (long long)DQK,
        (long long)NH_ * S_ * S_, (long long)S_ * S_,
        NH_, scale);

    softmax_split_kernel<<<dim3(S_, B_ * NH_), 256>>>(p_sc, at_h, at_l);

    // ao[z] = attn_z @ V_z   [2048 x 128] K=2048  (B = v packed [key][h*128+d], non-trans)
    bgemm_kernel<false><<<dim3(1, S_ / 128, B_ * NH_), 256>>>(
        at_h, at_l, v_h, v_l, p_ao, S_, DV_, S_,
        S_, NH_ * DV_, NH_ * DV_,
        (long long)NH_ * S_ * S_, (long long)S_ * S_,
        (long long)S_ * NH_ * DV_, (long long)DV_,
        (long long)S_ * NH_ * DV_, (long long)DV_,
        NH_, 1.f);

    convert_split_kernel<<<cvblocks((long long)M_ * NH_ * DV_), 256>>>(p_ao, ao_h, ao_l, (long long)M_ * NH_ * DV_);

    // out = ao @ wo^T   [4096 x 2048] K=2048
    bgemm_kernel<true><<<dim3(H_ / 128, M_ / 128, 1), 256>>>(
        ao_h, ao_l, wo_h, wo_l, out, M_, H_, NH_ * DV_, NH_ * DV_, NH_ * DV_, H_,
        0, 0, 0, 0, 0, 0, 1, 1.f);
}

// round 5
// speedup vs baseline: 2.7453x; 1.5912x over previous
#include <cuda_runtime.h>
#include <cuda_fp16.h>
#include <math.h>
#include <stdint.h>

// ---------------- problem constants ----------------
#define B_    2
#define S_    2048
#define H_    2048
#define NH_   16
#define QLORA 1536
#define KVLORA 512
#define DNOPE 128
#define DROPE 64
#define DV_   128
#define DQK   192
#define M_    (B_ * S_)    // 4096

// ---------------- fp32 scratch ----------------
__device__ __align__(16) float g_qa  [(size_t)M_ * QLORA];
__device__ __align__(16) float g_q   [(size_t)M_ * (NH_ * DQK)];
__device__ __align__(16) float g_kv  [(size_t)M_ * (KVLORA + DROPE)];
__device__ __align__(16) float g_kpe [(size_t)M_ * DROPE];
__device__ __align__(16) float g_kvx [(size_t)M_ * (NH_ * (DNOPE + DV_))];
__device__ __align__(16) float g_sc  [(size_t)B_ * NH_ * S_ * S_];   // 536 MB
__device__ __align__(16) float g_ao  [(size_t)M_ * (NH_ * DV_)];
__device__ float g_cos [S_ * (DROPE / 2)];
__device__ float g_sin [S_ * (DROPE / 2)];

// ---------------- fp16 split (hi/lo) operand buffers ----------------
__device__ __align__(16) __half g_hs_h [(size_t)M_ * H_],            g_hs_l [(size_t)M_ * H_];
__device__ __align__(16) __half g_wqa_h[(size_t)QLORA * H_],         g_wqa_l[(size_t)QLORA * H_];
__device__ __align__(16) __half g_wqb_h[(size_t)NH_ * DQK * QLORA],  g_wqb_l[(size_t)NH_ * DQK * QLORA];
__device__ __align__(16) __half g_wkva_h[(size_t)(KVLORA + DROPE) * H_], g_wkva_l[(size_t)(KVLORA + DROPE) * H_];
__device__ __align__(16) __half g_wkvb_h[(size_t)NH_ * (DNOPE + DV_) * KVLORA], g_wkvb_l[(size_t)NH_ * (DNOPE + DV_) * KVLORA];
__device__ __align__(16) __half g_wo_h [(size_t)H_ * NH_ * DV_],     g_wo_l [(size_t)H_ * NH_ * DV_];
__device__ __align__(16) __half g_qa_h [(size_t)M_ * QLORA],         g_qa_l [(size_t)M_ * QLORA];
__device__ __align__(16) __half g_qh   [(size_t)M_ * NH_ * DQK],     g_ql   [(size_t)M_ * NH_ * DQK];
__device__ __align__(16) __half g_kvc_h[(size_t)M_ * KVLORA],        g_kvc_l[(size_t)M_ * KVLORA];
__device__ __align__(16) __half g_kf_h [(size_t)M_ * NH_ * DQK],     g_kf_l [(size_t)M_ * NH_ * DQK];
__device__ __align__(16) __half g_vt_h [(size_t)B_ * NH_ * DV_ * S_], g_vt_l [(size_t)B_ * NH_ * DV_ * S_];
__device__ __align__(16) __half g_at_h [(size_t)B_ * NH_ * S_ * S_];  // probs, hi only (268 MB)
__device__ __align__(16) __half g_ao_h [(size_t)M_ * NH_ * DV_],     g_ao_l [(size_t)M_ * NH_ * DV_];

// ---------------- helpers ----------------
__device__ __forceinline__ void split_write(float v, __half* ph, __half* pl) {
    __half h = __float2half_rn(v);
    *ph = h;
    *pl = __float2half_rn(v - __half2float(h));
}

__device__ __forceinline__ uint32_t smem_u32(const void* p) {
    uint32_t a;
    asm("{ .reg .u64 t; cvta.to.shared.u64 t, %1; cvt.u32.u64 %0, t; }" : "=r"(a) : "l"(p));
    return a;
}

__device__ __forceinline__ void cp16(uint32_t dst, const void* src, bool pred) {
    int sz = pred ? 16 : 0;
    asm volatile("cp.async.cg.shared.global [%0], [%1], 16, %2;\n"
                 :: "r"(dst), "l"(src), "r"(sz));
}
#define CP_COMMIT()   asm volatile("cp.async.commit_group;\n" ::: "memory")
#define CP_WAIT(n)    asm volatile("cp.async.wait_group %0;\n" :: "n"(n) : "memory")

__device__ __forceinline__ void mma_fp16(float* c, const uint32_t* a, const uint32_t* b) {
    asm volatile(
        "mma.sync.aligned.m16n8k16.row.col.f32.f16.f16.f32 "
        "{%0,%1,%2,%3}, {%4,%5,%6,%7}, {%8,%9}, {%0,%1,%2,%3};\n"
        : "+f"(c[0]), "+f"(c[1]), "+f"(c[2]), "+f"(c[3])
        : "r"(a[0]), "r"(a[1]), "r"(a[2]), "r"(a[3]), "r"(b[0]), "r"(b[1]));
}

// ---------------- pipelined split fp16 tensor-core GEMM ----------------
// C[m,n] = alpha * sum_k A[m,k] * B[n,k]   (B row-major [n][k], K-contiguous)
// A = Ah + Al (fp16 hi/lo), B = Bh + Bl.
//   ASPLIT=true : 3 MMAs (AhBh + AhBl + AlBh)
//   ASPLIT=false: 2 MMAs (AhBh + AhBl), Al unused
// Tile 128x128, K-chunk 32, 2-stage cp.async pipeline, 256 thr, 2 CTA/SM.
// smem per stage: Ah(10240) Al(10240) Bh(10240) Bl(10240) ; stride 40 halves (80B rows)
#define STG_A_H 0
#define STG_A_L 10240
#define STG_B_H 20480
#define STG_B_L 30720
#define STG_BYTES 40960
#define GEMM_SMEM (2 * STG_BYTES)

extern __shared__ char sm_raw[];

template<bool ASPLIT>
__global__ void __launch_bounds__(256, 2)
hgemm(const __half* __restrict__ Ah, const __half* __restrict__ Al,
      const __half* __restrict__ Bh, const __half* __restrict__ Bl,
      float* __restrict__ C,
      int N, int K, int lda, int ldb, int ldc,
      long long sAb, long long sAhh, long long sBb, long long sBhh,
      long long sCb, long long sChh, int nh, float alpha)
{
    const int z = blockIdx.z;
    const int bb = z / nh, hh = z % nh;
    Ah += bb * sAb + hh * sAhh;  Al += bb * sAb + hh * sAhh;
    Bh += bb * sBb + hh * sBhh;  Bl += bb * sBb + hh * sBhh;
    C  += bb * sCb + hh * sChh;

    const int tid = threadIdx.x;
    const int lane = tid & 31, w = tid >> 5;
    const int wm = (w >> 1) * 32, wn = (w & 1) * 64;
    const int m0 = blockIdx.y * 128, n0 = blockIdx.x * 128;
    const int fr = lane >> 2, fc = (lane & 3) * 2;
    const int nk = K >> 5;                 // K multiple of 32 at all call sites

    const uint32_t smem = smem_u32(sm_raw);

    // loader: thread handles rows (tid>>2, tid>>2 or +64) chunk (tid&3)
    const int lrow0 = tid >> 2, lch = tid & 3;
    const __half* gA_h = Ah + (long long)(m0 + lrow0) * lda + lch * 8;
    const __half* gA_l = Al + (long long)(m0 + lrow0) * lda + lch * 8;
    const __half* gA_h2 = gA_h + 64ll * lda;
    const __half* gA_l2 = gA_l + 64ll * lda;
    const bool bp1 = (n0 + lrow0) < N;
    const bool bp2 = (n0 + lrow0 + 64) < N;
    const __half* gB_h  = Bh + (long long)(n0 + (bp1 ? lrow0 : 0)) * ldb + lch * 8;
    const __half* gB_l  = Bl + (long long)(n0 + (bp1 ? lrow0 : 0)) * ldb + lch * 8;
    const __half* gB_h2 = Bh + (long long)(n0 + (bp2 ? lrow0 + 64 : 0)) * ldb + lch * 8;
    const __half* gB_l2 = Bl + (long long)(n0 + (bp2 ? lrow0 + 64 : 0)) * ldb + lch * 8;
    const uint32_t so1 = (uint32_t)(lrow0 * 80 + lch * 16);
    const uint32_t so2 = (uint32_t)((lrow0 + 64) * 80 + lch * 16);

    auto load_stage = [&](int kc, int st) {
        uint32_t sb = smem + st * STG_BYTES;
        cp16(sb + STG_A_H + so1, gA_h  + kc, true);
        cp16(sb + STG_A_H + so2, gA_h2 + kc, true);
        if (ASPLIT) {
            cp16(sb + STG_A_L + so1, gA_l  + kc, true);
            cp16(sb + STG_A_L + so2, gA_l2 + kc, true);
        }
        cp16(sb + STG_B_H + so1, gB_h  + kc, bp1);
        cp16(sb + STG_B_H + so2, gB_h2 + kc, bp2);
        cp16(sb + STG_B_L + so1, gB_l  + kc, bp1);
        cp16(sb + STG_B_L + so2, gB_l2 + kc, bp2);
        CP_COMMIT();
    };

    float acc[2][8][4] = {};

    load_stage(0, 0);

    for (int k = 0; k < nk; k++) {
        const int st = k & 1;
        if (k + 1 < nk) {
            load_stage((k + 1) * 32, (k + 1) & 1);
            CP_WAIT(1);
        } else {
            CP_WAIT(0);
        }
        __syncthreads();

        const __half* sAh = (const __half*)(sm_raw + st * STG_BYTES + STG_A_H);
        const __half* sAl = (const __half*)(sm_raw + st * STG_BYTES + STG_A_L);
        const __half* sBh = (const __half*)(sm_raw + st * STG_BYTES + STG_B_H);
        const __half* sBl = (const __half*)(sm_raw + st * STG_BYTES + STG_B_L);

#pragma unroll
        for (int ks = 0; ks < 2; ks++) {
            const int kb = ks * 16;
            uint32_t a_h[2][4], a_l[2][4];
#pragma unroll
            for (int mt = 0; mt < 2; mt++) {
                int row = wm + mt * 16 + fr;
                a_h[mt][0] = *(const uint32_t*)&sAh[row * 40 + kb + fc];
                a_h[mt][1] = *(const uint32_t*)&sAh[(row + 8) * 40 + kb + fc];
                a_h[mt][2] = *(const uint32_t*)&sAh[row * 40 + kb + fc + 8];
                a_h[mt][3] = *(const uint32_t*)&sAh[(row + 8) * 40 + kb + fc + 8];
                if (ASPLIT) {
                    a_l[mt][0] = *(const uint32_t*)&sAl[row * 40 + kb + fc];
                    a_l[mt][1] = *(const uint32_t*)&sAl[(row + 8) * 40 + kb + fc];
                    a_l[mt][2] = *(const uint32_t*)&sAl[row * 40 + kb + fc + 8];
                    a_l[mt][3] = *(const uint32_t*)&sAl[(row + 8) * 40 + kb + fc + 8];
                }
            }
#pragma unroll
            for (int nt = 0; nt < 8; nt++) {
                int col = wn + nt * 8 + fr;
                uint32_t b_h[2], b_l[2];
                b_h[0] = *(const uint32_t*)&sBh[col * 40 + kb + fc];
                b_h[1] = *(const uint32_t*)&sBh[col * 40 + kb + fc + 8];
                b_l[0] = *(const uint32_t*)&sBl[col * 40 + kb + fc];
                b_l[1] = *(const uint32_t*)&sBl[col * 40 + kb + fc + 8];
#pragma unroll
                for (int mt = 0; mt < 2; mt++) {
                    mma_fp16(acc[mt][nt], a_h[mt], b_h);
                    mma_fp16(acc[mt][nt], a_h[mt], b_l);
                    if (ASPLIT) mma_fp16(acc[mt][nt], a_l[mt], b_h);
                }
            }
        }
        __syncthreads();
    }

    // epilogue
#pragma unroll
    for (int mt = 0; mt < 2; mt++) {
        int row = m0 + wm + mt * 16 + fr;
#pragma unroll
        for (int nt = 0; nt < 8; nt++) {
            int col = n0 + wn + nt * 8 + fc;
            if (col < N) {
                C[(long long)row * ldc + col]           = alpha * acc[mt][nt][0];
                C[(long long)row * ldc + col + 1]       = alpha * acc[mt][nt][1];
                C[(long long)(row + 8) * ldc + col]     = alpha * acc[mt][nt][2];
                C[(long long)(row + 8) * ldc + col + 1] = alpha * acc[mt][nt][3];
            }
        }
    }
}

// ---------------- fp32 -> (hi,lo) fp16 convert ----------------
__global__ void convert_split_kernel(const float* __restrict__ x,
                                     __half* __restrict__ h,
                                     __half* __restrict__ l, long long n)
{
    long long i = (long long)blockIdx.x * 256 + threadIdx.x;
    if (i < n) split_write(x[i], h + i, l + i);
}

// ---------------- RMSNorm -> split fp16 ----------------
__global__ void __launch_bounds__(256)
rmsnorm_split_kernel(const float* __restrict__ x, int ldx, const float* __restrict__ w,
                     __half* __restrict__ yh, __half* __restrict__ yl,
                     int ldy, int cols)
{
    const int row = blockIdx.x;
    const float* xr = x + (long long)row * ldx;
    float ss = 0.f;
    for (int c = threadIdx.x; c < cols; c += 256) { float v = xr[c]; ss += v * v; }
    __shared__ float red[256];
    red[threadIdx.x] = ss;
    __syncthreads();
    for (int s = 128; s > 0; s >>= 1) {
        if (threadIdx.x < s) red[threadIdx.x] += red[threadIdx.x + s];
        __syncthreads();
    }
    float inv = 1.f / sqrtf(red[0] / (float)cols + 1e-6f);
    long long base = (long long)row * ldy;
    for (int c = threadIdx.x; c < cols; c += 256)
        split_write(w[c] * xr[c] * inv, yh + base + c, yl + base + c);
}

// ---------------- RoPE ----------------
__global__ void freqs_kernel(float* __restrict__ cosd, float* __restrict__ sind)
{
    int t = blockIdx.x, i = threadIdx.x;
    double inv = pow(10000.0, -(double)(2 * i) / (double)DROPE);
    double f = (double)t * inv;
    cosd[t * 32 + i] = (float)cos(f);
    sind[t * 32 + i] = (float)sin(f);
}

__global__ void __launch_bounds__(512)
rope_q_kernel(float* __restrict__ q, const float* __restrict__ cosd,
              const float* __restrict__ sind)
{
    int m = blockIdx.x;
    int t = m & (S_ - 1);
    int h = threadIdx.x >> 5, i = threadIdx.x & 31;
    float cs = cosd[t * 32 + i], sn = sind[t * 32 + i];
    long long base = (long long)m * (NH_ * DQK) + h * DQK + DNOPE + 2 * i;
    float e = q[base], o = q[base + 1];
    q[base]     = e * cs - o * sn;
    q[base + 1] = e * sn + o * cs;
}

__global__ void rope_k_kernel(const float* __restrict__ kv, float* __restrict__ kpe,
                              const float* __restrict__ cosd, const float* __restrict__ sind)
{
    int m = blockIdx.x;
    int t = m & (S_ - 1);
    int i = threadIdx.x;
    float cs = cosd[t * 32 + i], sn = sind[t * 32 + i];
    long long base = (long long)m * (KVLORA + DROPE) + KVLORA + 2 * i;
    float e = kv[base], o = kv[base + 1];
    kpe[m * DROPE + 2 * i]     = e * cs - o * sn;
    kpe[m * DROPE + 2 * i + 1] = e * sn + o * cs;
}

// ---------------- kf assembly (split fp16) ----------------
__global__ void build_kf_kernel(const float* __restrict__ kvx, const float* __restrict__ kpe,
                                __half* __restrict__ kfh, __half* __restrict__ kfl)
{
    long long idx = (long long)blockIdx.x * 256 + threadIdx.x;
    int col = (int)(idx % (NH_ * DQK));
    long long m = idx / (NH_ * DQK);
    int h = col / DQK, d = col % DQK;
    float v;
    if (d < DNOPE) v = kvx[m * (NH_ * (DNOPE + DV_)) + h * (DNOPE + DV_) + d];
    else           v = kpe[m * DROPE + (d - DNOPE)];
    split_write(v, kfh + idx, kfl + idx);
}

// ---------------- V extraction + transpose: vt[b][h][d][s] ----------------
__global__ void __launch_bounds__(256)
transpose_v_kernel(const float* __restrict__ kvx,
                   __half* __restrict__ vth, __half* __restrict__ vtl)
{
    __shared__ float t[32][33];
    int z = blockIdx.z;
    int b = z / NH_, h = z % NH_;
    int s0 = blockIdx.x * 32, d0 = blockIdx.y * 32;
    int tx = threadIdx.x & 31, ty = threadIdx.x >> 5;
#pragma unroll
    for (int i = ty; i < 32; i += 8)
        t[i][tx] = kvx[((long long)(b * S_ + s0 + i)) * (NH_ * (DNOPE + DV_))
                       + h * (DNOPE + DV_) + DNOPE + d0 + tx];
    __syncthreads();
#pragma unroll
    for (int i = ty; i < 32; i += 8) {
        long long o = ((long long)z * DV_ + d0 + i) * S_ + s0 + tx;
        split_write(t[tx][i], vth + o, vtl + o);
    }
}

// ---------------- softmax -> fp16 (hi only) ----------------
__global__ void __launch_bounds__(256)
softmax_kernel(const float* __restrict__ s, __half* __restrict__ ah)
{
    long long off = ((long long)blockIdx.y * S_ + blockIdx.x) * (long long)S_;
    const float* row = s + off;
    __shared__ float red[256];
    float mx = -1e30f;
    for (int c = threadIdx.x; c < S_; c += 256) mx = fmaxf(mx, row[c]);
    red[threadIdx.x] = mx;
    __syncthreads();
    for (int st = 128; st > 0; st >>= 1) {
        if (threadIdx.x < st) red[threadIdx.x] = fmaxf(red[threadIdx.x], red[threadIdx.x + st]);
        __syncthreads();
    }
    mx = red[0];
    __syncthreads();
    float sum = 0.f;
    for (int c = threadIdx.x; c < S_; c += 256) sum += __expf(row[c] - mx);
    red[threadIdx.x] = sum;
    __syncthreads();
    for (int st = 128; st > 0; st >>= 1) {
        if (threadIdx.x < st) red[threadIdx.x] += red[threadIdx.x + st];
        __syncthreads();
    }
    float inv = 1.f / red[0];
    for (int c = threadIdx.x; c < S_; c += 256)
        ah[off + c] = __float2half_rn(__expf(row[c] - mx) * inv);
}

// ---------------- launch ----------------
extern "C" void kernel_launch(void* const* d_in, const int* in_sizes, int n_in,
                              void* d_out, int out_size)
{
    const float* hs        = (const float*)d_in[0];
    const float* wq_a      = (const float*)d_in[1];
    const float* q_norm_w  = (const float*)d_in[2];
    const float* wq_b      = (const float*)d_in[3];
    const float* wkv_a     = (const float*)d_in[4];
    const float* kv_norm_w = (const float*)d_in[5];
    const float* wkv_b     = (const float*)d_in[6];
    const float* wo        = (const float*)d_in[7];
    float* out = (float*)d_out;

    cudaFuncSetAttribute(hgemm<true>,  cudaFuncAttributeMaxDynamicSharedMemorySize, GEMM_SMEM);
    cudaFuncSetAttribute(hgemm<false>, cudaFuncAttributeMaxDynamicSharedMemorySize, GEMM_SMEM);

    float *p_qa, *p_q, *p_kv, *p_kpe, *p_kvx, *p_sc, *p_ao, *p_cos, *p_sin;
    cudaGetSymbolAddress((void**)&p_qa,  g_qa);
    cudaGetSymbolAddress((void**)&p_q,   g_q);
    cudaGetSymbolAddress((void**)&p_kv,  g_kv);
    cudaGetSymbolAddress((void**)&p_kpe, g_kpe);
    cudaGetSymbolAddress((void**)&p_kvx, g_kvx);
    cudaGetSymbolAddress((void**)&p_sc,  g_sc);
    cudaGetSymbolAddress((void**)&p_ao,  g_ao);
    cudaGetSymbolAddress((void**)&p_cos, g_cos);
    cudaGetSymbolAddress((void**)&p_sin, g_sin);

    __half *hs_h, *hs_l, *wqa_h, *wqa_l, *wqb_h, *wqb_l, *wkva_h, *wkva_l;
    __half *wkvb_h, *wkvb_l, *wo_h, *wo_l, *qa_h, *qa_l, *q_h, *q_l;
    __half *kvc_h, *kvc_l, *kf_h, *kf_l, *vt_h, *vt_l, *at_h, *ao_h, *ao_l;
    cudaGetSymbolAddress((void**)&hs_h,  g_hs_h);   cudaGetSymbolAddress((void**)&hs_l,  g_hs_l);
    cudaGetSymbolAddress((void**)&wqa_h, g_wqa_h);  cudaGetSymbolAddress((void**)&wqa_l, g_wqa_l);
    cudaGetSymbolAddress((void**)&wqb_h, g_wqb_h);  cudaGetSymbolAddress((void**)&wqb_l, g_wqb_l);
    cudaGetSymbolAddress((void**)&wkva_h, g_wkva_h); cudaGetSymbolAddress((void**)&wkva_l, g_wkva_l);
    cudaGetSymbolAddress((void**)&wkvb_h, g_wkvb_h); cudaGetSymbolAddress((void**)&wkvb_l, g_wkvb_l);
    cudaGetSymbolAddress((void**)&wo_h,  g_wo_h);   cudaGetSymbolAddress((void**)&wo_l,  g_wo_l);
    cudaGetSymbolAddress((void**)&qa_h,  g_qa_h);   cudaGetSymbolAddress((void**)&qa_l,  g_qa_l);
    cudaGetSymbolAddress((void**)&q_h,   g_qh);     cudaGetSymbolAddress((void**)&q_l,   g_ql);
    cudaGetSymbolAddress((void**)&kvc_h, g_kvc_h);  cudaGetSymbolAddress((void**)&kvc_l, g_kvc_l);
    cudaGetSymbolAddress((void**)&kf_h,  g_kf_h);   cudaGetSymbolAddress((void**)&kf_l,  g_kf_l);
    cudaGetSymbolAddress((void**)&vt_h,  g_vt_h);   cudaGetSymbolAddress((void**)&vt_l,  g_vt_l);
    cudaGetSymbolAddress((void**)&at_h,  g_at_h);
    cudaGetSymbolAddress((void**)&ao_h,  g_ao_h);   cudaGetSymbolAddress((void**)&ao_l,  g_ao_l);

    const float scale = 1.0f / sqrtf((float)DQK);
    auto cvblocks = [](long long n) { return (int)((n + 255) / 256); };
    auto ntiles = [](int n) { return (n + 127) / 128; };

    freqs_kernel<<<S_, 32>>>(p_cos, p_sin);

    // input conversions
    convert_split_kernel<<<cvblocks((long long)M_ * H_), 256>>>(hs, hs_h, hs_l, (long long)M_ * H_);
    convert_split_kernel<<<cvblocks((long long)QLORA * H_), 256>>>(wq_a, wqa_h, wqa_l, (long long)QLORA * H_);
    convert_split_kernel<<<cvblocks((long long)NH_ * DQK * QLORA), 256>>>(wq_b, wqb_h, wqb_l, (long long)NH_ * DQK * QLORA);
    convert_split_kernel<<<cvblocks((long long)(KVLORA + DROPE) * H_), 256>>>(wkv_a, wkva_h, wkva_l, (long long)(KVLORA + DROPE) * H_);
    convert_split_kernel<<<cvblocks((long long)NH_ * (DNOPE + DV_) * KVLORA), 256>>>(wkv_b, wkvb_h, wkvb_l, (long long)NH_ * (DNOPE + DV_) * KVLORA);
    convert_split_kernel<<<cvblocks((long long)H_ * NH_ * DV_), 256>>>(wo, wo_h, wo_l, (long long)H_ * NH_ * DV_);

    // q_a = hs @ wq_a^T   [4096 x 1536] K=2048
    hgemm<true><<<dim3(ntiles(QLORA), M_ / 128, 1), 256, GEMM_SMEM>>>(
        hs_h, hs_l, wqa_h, wqa_l, p_qa, QLORA, H_, H_, H_, QLORA,
        0, 0, 0, 0, 0, 0, 1, 1.f);

    rmsnorm_split_kernel<<<M_, 256>>>(p_qa, QLORA, q_norm_w, qa_h, qa_l, QLORA, QLORA);

    // q = q_a @ wq_b^T    [4096 x 3072] K=1536
    hgemm<true><<<dim3(ntiles(NH_ * DQK), M_ / 128, 1), 256, GEMM_SMEM>>>(
        qa_h, qa_l, wqb_h, wqb_l, p_q, NH_ * DQK, QLORA, QLORA, QLORA, NH_ * DQK,
        0, 0, 0, 0, 0, 0, 1, 1.f);

    // kv = hs @ wkv_a^T   [4096 x 576] K=2048
    hgemm<true><<<dim3(ntiles(KVLORA + DROPE), M_ / 128, 1), 256, GEMM_SMEM>>>(
        hs_h, hs_l, wkva_h, wkva_l, p_kv, KVLORA + DROPE, H_, H_, H_, KVLORA + DROPE,
        0, 0, 0, 0, 0, 0, 1, 1.f);

    rmsnorm_split_kernel<<<M_, 256>>>(p_kv, KVLORA + DROPE, kv_norm_w, kvc_h, kvc_l, KVLORA, KVLORA);
    rope_k_kernel<<<M_, 32>>>(p_kv, p_kpe, p_cos, p_sin);

    // kv_x = kv_c @ wkv_b^T  [4096 x 4096] K=512
    hgemm<true><<<dim3(ntiles(NH_ * (DNOPE + DV_)), M_ / 128, 1), 256, GEMM_SMEM>>>(
        kvc_h, kvc_l, wkvb_h, wkvb_l, p_kvx, NH_ * (DNOPE + DV_), KVLORA, KVLORA, KVLORA,
        NH_ * (DNOPE + DV_), 0, 0, 0, 0, 0, 0, 1, 1.f);

    rope_q_kernel<<<M_, 512>>>(p_q, p_cos, p_sin);
    convert_split_kernel<<<cvblocks((long long)M_ * NH_ * DQK), 256>>>(p_q, q_h, q_l, (long long)M_ * NH_ * DQK);
    build_kf_kernel<<<cvblocks((long long)M_ * NH_ * DQK), 256>>>(p_kvx, p_kpe, kf_h, kf_l);
    transpose_v_kernel<<<dim3(S_ / 32, DV_ / 32, B_ * NH_), 256>>>(p_kvx, vt_h, vt_l);

    // scores[z] = scale * Q_z @ Kf_z^T   [2048 x 2048] K=192
    hgemm<true><<<dim3(ntiles(S_), S_ / 128, B_ * NH_), 256, GEMM_SMEM>>>(
        q_h, q_l, kf_h, kf_l, p_sc, S_, DQK,
        NH_ * DQK, NH_ * DQK, S_,
        (long long)S_ * NH_ * DQK, (long long)DQK,
        (long long)S_ * NH_ * DQK, (long long)DQK,
        (long long)NH_ * S_ * S_, (long long)S_ * S_,
        NH_, scale);

    softmax_kernel<<<dim3(S_, B_ * NH_), 256>>>(p_sc, at_h);

    // ao[z] = attn_z @ Vt_z^T  [2048 x 128] K=2048 ; probs plain fp16, V split
    hgemm<false><<<dim3(1, S_ / 128, B_ * NH_), 256, GEMM_SMEM>>>(
        at_h, at_h, vt_h, vt_l, p_ao, DV_, S_,
        S_, S_, NH_ * DV_,
        (long long)NH_ * S_ * S_, (long long)S_ * S_,
        (long long)NH_ * DV_ * S_, (long long)DV_ * S_,
        (long long)S_ * NH_ * DV_, (long long)DV_,
        NH_, 1.f);

    convert_split_kernel<<<cvblocks((long long)M_ * NH_ * DV_), 256>>>(p_ao, ao_h, ao_l, (long long)M_ * NH_ * DV_);

    // out = ao @ wo^T   [4096 x 2048] K=2048
    hgemm<true><<<dim3(ntiles(H_), M_ / 128, 1), 256, GEMM_SMEM>>>(
        ao_h, ao_l, wo_h, wo_l, out, H_, NH_ * DV_, NH_ * DV_, NH_ * DV_, H_,
        0, 0, 0, 0, 0, 0, 1, 1.f);
}

// round 6
// speedup vs baseline: 2.8963x; 1.0550x over previous
#include <cuda_runtime.h>
#include <cuda_fp16.h>
#include <math.h>
#include <stdint.h>

// ---------------- problem constants ----------------
#define B_    2
#define S_    2048
#define H_    2048
#define NH_   16
#define QLORA 1536
#define KVLORA 512
#define DNOPE 128
#define DROPE 64
#define DV_   128
#define DQK   192
#define M_    (B_ * S_)    // 4096

// ---------------- fp32 scratch ----------------
__device__ __align__(16) float g_qa  [(size_t)M_ * QLORA];
__device__ __align__(16) float g_q   [(size_t)M_ * (NH_ * DQK)];
__device__ __align__(16) float g_kv  [(size_t)M_ * (KVLORA + DROPE)];
__device__ __align__(16) float g_kpe [(size_t)M_ * DROPE];
__device__ __align__(16) float g_kvx [(size_t)M_ * (NH_ * (DNOPE + DV_))];
__device__ __align__(16) float g_sc  [(size_t)B_ * NH_ * S_ * S_];   // 536 MB
__device__ __align__(16) float g_ao  [(size_t)M_ * (NH_ * DV_)];
__device__ float g_cos [S_ * (DROPE / 2)];
__device__ float g_sin [S_ * (DROPE / 2)];

// ---------------- fp16 split (hi/lo) operand buffers ----------------
__device__ __align__(16) __half g_hs_h [(size_t)M_ * H_],            g_hs_l [(size_t)M_ * H_];
__device__ __align__(16) __half g_wqa_h[(size_t)QLORA * H_],         g_wqa_l[(size_t)QLORA * H_];
__device__ __align__(16) __half g_wqb_h[(size_t)NH_ * DQK * QLORA],  g_wqb_l[(size_t)NH_ * DQK * QLORA];
__device__ __align__(16) __half g_wkva_h[(size_t)(KVLORA + DROPE) * H_], g_wkva_l[(size_t)(KVLORA + DROPE) * H_];
__device__ __align__(16) __half g_wkvb_h[(size_t)NH_ * (DNOPE + DV_) * KVLORA], g_wkvb_l[(size_t)NH_ * (DNOPE + DV_) * KVLORA];
__device__ __align__(16) __half g_wo_h [(size_t)H_ * NH_ * DV_],     g_wo_l [(size_t)H_ * NH_ * DV_];
__device__ __align__(16) __half g_qa_h [(size_t)M_ * QLORA],         g_qa_l [(size_t)M_ * QLORA];
__device__ __align__(16) __half g_qh   [(size_t)M_ * NH_ * DQK],     g_ql   [(size_t)M_ * NH_ * DQK];
__device__ __align__(16) __half g_kvc_h[(size_t)M_ * KVLORA],        g_kvc_l[(size_t)M_ * KVLORA];
__device__ __align__(16) __half g_kf_h [(size_t)M_ * NH_ * DQK],     g_kf_l [(size_t)M_ * NH_ * DQK];
__device__ __align__(16) __half g_vt_h [(size_t)B_ * NH_ * DV_ * S_], g_vt_l [(size_t)B_ * NH_ * DV_ * S_];
__device__ __align__(16) __half g_at_h [(size_t)B_ * NH_ * S_ * S_];  // probs, hi only (268 MB)
__device__ __align__(16) __half g_ao_h [(size_t)M_ * NH_ * DV_],     g_ao_l [(size_t)M_ * NH_ * DV_];

// ---------------- helpers ----------------
__device__ __forceinline__ void split_write(float v, __half* ph, __half* pl) {
    __half h = __float2half_rn(v);
    *ph = h;
    *pl = __float2half_rn(v - __half2float(h));
}

__device__ __forceinline__ uint32_t smem_u32(const void* p) {
    uint32_t a;
    asm("{ .reg .u64 t; cvta.to.shared.u64 t, %1; cvt.u32.u64 %0, t; }" : "=r"(a) : "l"(p));
    return a;
}

__device__ __forceinline__ void cp16(uint32_t dst, const void* src, bool pred) {
    int sz = pred ? 16 : 0;
    asm volatile("cp.async.cg.shared.global [%0], [%1], 16, %2;\n"
                 :: "r"(dst), "l"(src), "r"(sz));
}
#define CP_COMMIT()   asm volatile("cp.async.commit_group;\n" ::: "memory")
#define CP_WAIT(n)    asm volatile("cp.async.wait_group %0;\n" :: "n"(n) : "memory")

__device__ __forceinline__ void mma_fp16(float* c, const uint32_t* a, const uint32_t* b) {
    asm volatile(
        "mma.sync.aligned.m16n8k16.row.col.f32.f16.f16.f32 "
        "{%0,%1,%2,%3}, {%4,%5,%6,%7}, {%8,%9}, {%0,%1,%2,%3};\n"
        : "+f"(c[0]), "+f"(c[1]), "+f"(c[2]), "+f"(c[3])
        : "r"(a[0]), "r"(a[1]), "r"(a[2]), "r"(a[3]), "r"(b[0]), "r"(b[1]));
}

__device__ __forceinline__ void ldsm_x4(uint32_t* r, uint32_t addr) {
    asm volatile("ldmatrix.sync.aligned.m8n8.x4.shared.b16 {%0,%1,%2,%3}, [%4];"
        : "=r"(r[0]), "=r"(r[1]), "=r"(r[2]), "=r"(r[3]) : "r"(addr));
}

// ---------------- pipelined split fp16 tensor-core GEMM (ldmatrix mainloop) ----------------
// C[m,n] = alpha * sum_k A[m,k] * B[n,k]   (B row-major [n][k], K-contiguous)
// A = Ah + Al (fp16 hi/lo), B = Bh + Bl.
//   ASPLIT=true : 3 MMAs (AhBh + AhBl + AlBh)
//   ASPLIT=false: 2 MMAs (AhBh + AhBl), Al unused
// Tile 128x128, K-chunk 32, 2-stage cp.async pipeline, 256 thr, 2 CTA/SM.
// smem per stage: Ah(10240) Al(10240) Bh(10240) Bl(10240) ; stride 40 halves (80B rows)
#define STG_A_H 0
#define STG_A_L 10240
#define STG_B_H 20480
#define STG_B_L 30720
#define STG_BYTES 40960
#define GEMM_SMEM (2 * STG_BYTES)

extern __shared__ char sm_raw[];

template<bool ASPLIT>
__global__ void __launch_bounds__(256, 2)
hgemm(const __half* __restrict__ Ah, const __half* __restrict__ Al,
      const __half* __restrict__ Bh, const __half* __restrict__ Bl,
      float* __restrict__ C,
      int N, int K, int lda, int ldb, int ldc,
      long long sAb, long long sAhh, long long sBb, long long sBhh,
      long long sCb, long long sChh, int nh, float alpha)
{
    const int z = blockIdx.z;
    const int bb = z / nh, hh = z % nh;
    Ah += bb * sAb + hh * sAhh;  Al += bb * sAb + hh * sAhh;
    Bh += bb * sBb + hh * sBhh;  Bl += bb * sBb + hh * sBhh;
    C  += bb * sCb + hh * sChh;

    const int tid = threadIdx.x;
    const int lane = tid & 31, w = tid >> 5;
    const int wm = (w >> 1) * 32, wn = (w & 1) * 64;
    const int m0 = blockIdx.y * 128, n0 = blockIdx.x * 128;
    const int fr = lane >> 2, fc = (lane & 3) * 2;
    const int nk = K >> 5;                 // K multiple of 32 at all call sites

    const uint32_t smem = smem_u32(sm_raw);

    // ---- ldmatrix per-lane byte offsets (within A / B regions) ----
    uint32_t aoff[2], boff[4];
    {
        int r = wm + (lane & 15);
        int c = (lane >> 4) * 8;
        aoff[0] = (uint32_t)((r * 40 + c) * 2);
        aoff[1] = (uint32_t)(((r + 16) * 40 + c) * 2);
        int lnB = lane & 7;
        int pHi = lane >> 4;              // which nt within the pair
        int kh  = ((lane >> 3) & 1) * 8;  // k half
#pragma unroll
        for (int p = 0; p < 4; p++) {
            int n = wn + (2 * p + pHi) * 8 + lnB;
            boff[p] = (uint32_t)((n * 40 + kh) * 2);
        }
    }

    // loader: thread handles rows (tid>>2, +64) chunk (tid&3)
    const int lrow0 = tid >> 2, lch = tid & 3;
    const __half* gA_h = Ah + (long long)(m0 + lrow0) * lda + lch * 8;
    const __half* gA_l = Al + (long long)(m0 + lrow0) * lda + lch * 8;
    const __half* gA_h2 = gA_h + 64ll * lda;
    const __half* gA_l2 = gA_l + 64ll * lda;
    const bool bp1 = (n0 + lrow0) < N;
    const bool bp2 = (n0 + lrow0 + 64) < N;
    const __half* gB_h  = Bh + (long long)(n0 + (bp1 ? lrow0 : 0)) * ldb + lch * 8;
    const __half* gB_l  = Bl + (long long)(n0 + (bp1 ? lrow0 : 0)) * ldb + lch * 8;
    const __half* gB_h2 = Bh + (long long)(n0 + (bp2 ? lrow0 + 64 : 0)) * ldb + lch * 8;
    const __half* gB_l2 = Bl + (long long)(n0 + (bp2 ? lrow0 + 64 : 0)) * ldb + lch * 8;
    const uint32_t so1 = (uint32_t)(lrow0 * 80 + lch * 16);
    const uint32_t so2 = (uint32_t)((lrow0 + 64) * 80 + lch * 16);

    auto load_stage = [&](int kc, int st) {
        uint32_t sb = smem + st * STG_BYTES;
        cp16(sb + STG_A_H + so1, gA_h  + kc, true);
        cp16(sb + STG_A_H + so2, gA_h2 + kc, true);
        if (ASPLIT) {
            cp16(sb + STG_A_L + so1, gA_l  + kc, true);
            cp16(sb + STG_A_L + so2, gA_l2 + kc, true);
        }
        cp16(sb + STG_B_H + so1, gB_h  + kc, bp1);
        cp16(sb + STG_B_H + so2, gB_h2 + kc, bp2);
        cp16(sb + STG_B_L + so1, gB_l  + kc, bp1);
        cp16(sb + STG_B_L + so2, gB_l2 + kc, bp2);
        CP_COMMIT();
    };

    float acc[2][8][4] = {};

    load_stage(0, 0);

    for (int k = 0; k < nk; k++) {
        const int st = k & 1;
        if (k + 1 < nk) {
            load_stage((k + 1) * 32, (k + 1) & 1);
            CP_WAIT(1);
        } else {
            CP_WAIT(0);
        }
        __syncthreads();

        const uint32_t sb = smem + st * STG_BYTES;

#pragma unroll
        for (int ks = 0; ks < 2; ks++) {
            const uint32_t kB = ks * 32;   // 16 halves = 32 bytes
            uint32_t a_h[2][4], a_l[2][4];
#pragma unroll
            for (int mt = 0; mt < 2; mt++) {
                ldsm_x4(a_h[mt], sb + STG_A_H + aoff[mt] + kB);
                if (ASPLIT) ldsm_x4(a_l[mt], sb + STG_A_L + aoff[mt] + kB);
            }
#pragma unroll
            for (int p = 0; p < 4; p++) {
                uint32_t bh[4], bl[4];
                ldsm_x4(bh, sb + STG_B_H + boff[p] + kB);
                ldsm_x4(bl, sb + STG_B_L + boff[p] + kB);
#pragma unroll
                for (int sub = 0; sub < 2; sub++) {
                    const uint32_t* bph = bh + 2 * sub;
                    const uint32_t* bpl = bl + 2 * sub;
                    const int nt = 2 * p + sub;
#pragma unroll
                    for (int mt = 0; mt < 2; mt++) {
                        mma_fp16(acc[mt][nt], a_h[mt], bph);
                        mma_fp16(acc[mt][nt], a_h[mt], bpl);
                        if (ASPLIT) mma_fp16(acc[mt][nt], a_l[mt], bph);
                    }
                }
            }
        }
        __syncthreads();
    }

    // epilogue
#pragma unroll
    for (int mt = 0; mt < 2; mt++) {
        int row = m0 + wm + mt * 16 + fr;
#pragma unroll
        for (int nt = 0; nt < 8; nt++) {
            int col = n0 + wn + nt * 8 + fc;
            if (col < N) {
                C[(long long)row * ldc + col]           = alpha * acc[mt][nt][0];
                C[(long long)row * ldc + col + 1]       = alpha * acc[mt][nt][1];
                C[(long long)(row + 8) * ldc + col]     = alpha * acc[mt][nt][2];
                C[(long long)(row + 8) * ldc + col + 1] = alpha * acc[mt][nt][3];
            }
        }
    }
}

// ---------------- fp32 -> (hi,lo) fp16 convert ----------------
__global__ void convert_split_kernel(const float* __restrict__ x,
                                     __half* __restrict__ h,
                                     __half* __restrict__ l, long long n)
{
    long long i = (long long)blockIdx.x * 256 + threadIdx.x;
    if (i < n) split_write(x[i], h + i, l + i);
}

// ---------------- RMSNorm -> split fp16 ----------------
__global__ void __launch_bounds__(256)
rmsnorm_split_kernel(const float* __restrict__ x, int ldx, const float* __restrict__ w,
                     __half* __restrict__ yh, __half* __restrict__ yl,
                     int ldy, int cols)
{
    const int row = blockIdx.x;
    const float* xr = x + (long long)row * ldx;
    float ss = 0.f;
    for (int c = threadIdx.x; c < cols; c += 256) { float v = xr[c]; ss += v * v; }
    __shared__ float red[256];
    red[threadIdx.x] = ss;
    __syncthreads();
    for (int s = 128; s > 0; s >>= 1) {
        if (threadIdx.x < s) red[threadIdx.x] += red[threadIdx.x + s];
        __syncthreads();
    }
    float inv = 1.f / sqrtf(red[0] / (float)cols + 1e-6f);
    long long base = (long long)row * ldy;
    for (int c = threadIdx.x; c < cols; c += 256)
        split_write(w[c] * xr[c] * inv, yh + base + c, yl + base + c);
}

// ---------------- RoPE ----------------
__global__ void freqs_kernel(float* __restrict__ cosd, float* __restrict__ sind)
{
    int t = blockIdx.x, i = threadIdx.x;
    double inv = pow(10000.0, -(double)(2 * i) / (double)DROPE);
    double f = (double)t * inv;
    cosd[t * 32 + i] = (float)cos(f);
    sind[t * 32 + i] = (float)sin(f);
}

__global__ void __launch_bounds__(512)
rope_q_kernel(float* __restrict__ q, const float* __restrict__ cosd,
              const float* __restrict__ sind)
{
    int m = blockIdx.x;
    int t = m & (S_ - 1);
    int h = threadIdx.x >> 5, i = threadIdx.x & 31;
    float cs = cosd[t * 32 + i], sn = sind[t * 32 + i];
    long long base = (long long)m * (NH_ * DQK) + h * DQK + DNOPE + 2 * i;
    float e = q[base], o = q[base + 1];
    q[base]     = e * cs - o * sn;
    q[base + 1] = e * sn + o * cs;
}

__global__ void rope_k_kernel(const float* __restrict__ kv, float* __restrict__ kpe,
                              const float* __restrict__ cosd, const float* __restrict__ sind)
{
    int m = blockIdx.x;
    int t = m & (S_ - 1);
    int i = threadIdx.x;
    float cs = cosd[t * 32 + i], sn = sind[t * 32 + i];
    long long base = (long long)m * (KVLORA + DROPE) + KVLORA + 2 * i;
    float e = kv[base], o = kv[base + 1];
    kpe[m * DROPE + 2 * i]     = e * cs - o * sn;
    kpe[m * DROPE + 2 * i + 1] = e * sn + o * cs;
}

// ---------------- kf assembly (split fp16) ----------------
__global__ void build_kf_kernel(const float* __restrict__ kvx, const float* __restrict__ kpe,
                                __half* __restrict__ kfh, __half* __restrict__ kfl)
{
    long long idx = (long long)blockIdx.x * 256 + threadIdx.x;
    int col = (int)(idx % (NH_ * DQK));
    long long m = idx / (NH_ * DQK);
    int h = col / DQK, d = col % DQK;
    float v;
    if (d < DNOPE) v = kvx[m * (NH_ * (DNOPE + DV_)) + h * (DNOPE + DV_) + d];
    else           v = kpe[m * DROPE + (d - DNOPE)];
    split_write(v, kfh + idx, kfl + idx);
}

// ---------------- V extraction + transpose: vt[b][h][d][s] ----------------
__global__ void __launch_bounds__(256)
transpose_v_kernel(const float* __restrict__ kvx,
                   __half* __restrict__ vth, __half* __restrict__ vtl)
{
    __shared__ float t[32][33];
    int z = blockIdx.z;
    int b = z / NH_, h = z % NH_;
    int s0 = blockIdx.x * 32, d0 = blockIdx.y * 32;
    int tx = threadIdx.x & 31, ty = threadIdx.x >> 5;
#pragma unroll
    for (int i = ty; i < 32; i += 8)
        t[i][tx] = kvx[((long long)(b * S_ + s0 + i)) * (NH_ * (DNOPE + DV_))
                       + h * (DNOPE + DV_) + DNOPE + d0 + tx];
    __syncthreads();
#pragma unroll
    for (int i = ty; i < 32; i += 8) {
        long long o = ((long long)z * DV_ + d0 + i) * S_ + s0 + tx;
        split_write(t[tx][i], vth + o, vtl + o);
    }
}

// ---------------- softmax -> fp16 (hi only) ----------------
__global__ void __launch_bounds__(256)
softmax_kernel(const float* __restrict__ s, __half* __restrict__ ah)
{
    long long off = ((long long)blockIdx.y * S_ + blockIdx.x) * (long long)S_;
    const float* row = s + off;
    __shared__ float red[256];
    float mx = -1e30f;
    for (int c = threadIdx.x; c < S_; c += 256) mx = fmaxf(mx, row[c]);
    red[threadIdx.x] = mx;
    __syncthreads();
    for (int st = 128; st > 0; st >>= 1) {
        if (threadIdx.x < st) red[threadIdx.x] = fmaxf(red[threadIdx.x], red[threadIdx.x + st]);
        __syncthreads();
    }
    mx = red[0];
    __syncthreads();
    float sum = 0.f;
    for (int c = threadIdx.x; c < S_; c += 256) sum += __expf(row[c] - mx);
    red[threadIdx.x] = sum;
    __syncthreads();
    for (int st = 128; st > 0; st >>= 1) {
        if (threadIdx.x < st) red[threadIdx.x] += red[threadIdx.x + st];
        __syncthreads();
    }
    float inv = 1.f / red[0];
    for (int c = threadIdx.x; c < S_; c += 256)
        ah[off + c] = __float2half_rn(__expf(row[c] - mx) * inv);
}

// ---------------- launch ----------------
extern "C" void kernel_launch(void* const* d_in, const int* in_sizes, int n_in,
                              void* d_out, int out_size)
{
    const float* hs        = (const float*)d_in[0];
    const float* wq_a      = (const float*)d_in[1];
    const float* q_norm_w  = (const float*)d_in[2];
    const float* wq_b      = (const float*)d_in[3];
    const float* wkv_a     = (const float*)d_in[4];
    const float* kv_norm_w = (const float*)d_in[5];
    const float* wkv_b     = (const float*)d_in[6];
    const float* wo        = (const float*)d_in[7];
    float* out = (float*)d_out;

    cudaFuncSetAttribute(hgemm<true>,  cudaFuncAttributeMaxDynamicSharedMemorySize, GEMM_SMEM);
    cudaFuncSetAttribute(hgemm<false>, cudaFuncAttributeMaxDynamicSharedMemorySize, GEMM_SMEM);

    float *p_qa, *p_q, *p_kv, *p_kpe, *p_kvx, *p_sc, *p_ao, *p_cos, *p_sin;
    cudaGetSymbolAddress((void**)&p_qa,  g_qa);
    cudaGetSymbolAddress((void**)&p_q,   g_q);
    cudaGetSymbolAddress((void**)&p_kv,  g_kv);
    cudaGetSymbolAddress((void**)&p_kpe, g_kpe);
    cudaGetSymbolAddress((void**)&p_kvx, g_kvx);
    cudaGetSymbolAddress((void**)&p_sc,  g_sc);
    cudaGetSymbolAddress((void**)&p_ao,  g_ao);
    cudaGetSymbolAddress((void**)&p_cos, g_cos);
    cudaGetSymbolAddress((void**)&p_sin, g_sin);

    __half *hs_h, *hs_l, *wqa_h, *wqa_l, *wqb_h, *wqb_l, *wkva_h, *wkva_l;
    __half *wkvb_h, *wkvb_l, *wo_h, *wo_l, *qa_h, *qa_l, *q_h, *q_l;
    __half *kvc_h, *kvc_l, *kf_h, *kf_l, *vt_h, *vt_l, *at_h, *ao_h, *ao_l;
    cudaGetSymbolAddress((void**)&hs_h,  g_hs_h);   cudaGetSymbolAddress((void**)&hs_l,  g_hs_l);
    cudaGetSymbolAddress((void**)&wqa_h, g_wqa_h);  cudaGetSymbolAddress((void**)&wqa_l, g_wqa_l);
    cudaGetSymbolAddress((void**)&wqb_h, g_wqb_h);  cudaGetSymbolAddress((void**)&wqb_l, g_wqb_l);
    cudaGetSymbolAddress((void**)&wkva_h, g_wkva_h); cudaGetSymbolAddress((void**)&wkva_l, g_wkva_l);
    cudaGetSymbolAddress((void**)&wkvb_h, g_wkvb_h); cudaGetSymbolAddress((void**)&wkvb_l, g_wkvb_l);
    cudaGetSymbolAddress((void**)&wo_h,  g_wo_h);   cudaGetSymbolAddress((void**)&wo_l,  g_wo_l);
    cudaGetSymbolAddress((void**)&qa_h,  g_qa_h);   cudaGetSymbolAddress((void**)&qa_l,  g_qa_l);
    cudaGetSymbolAddress((void**)&q_h,   g_qh);     cudaGetSymbolAddress((void**)&q_l,   g_ql);
    cudaGetSymbolAddress((void**)&kvc_h, g_kvc_h);  cudaGetSymbolAddress((void**)&kvc_l, g_kvc_l);
    cudaGetSymbolAddress((void**)&kf_h,  g_kf_h);   cudaGetSymbolAddress((void**)&kf_l,  g_kf_l);
    cudaGetSymbolAddress((void**)&vt_h,  g_vt_h);   cudaGetSymbolAddress((void**)&vt_l,  g_vt_l);
    cudaGetSymbolAddress((void**)&at_h,  g_at_h);
    cudaGetSymbolAddress((void**)&ao_h,  g_ao_h);   cudaGetSymbolAddress((void**)&ao_l,  g_ao_l);

    const float scale = 1.0f / sqrtf((float)DQK);
    auto cvblocks = [](long long n) { return (int)((n + 255) / 256); };
    auto ntiles = [](int n) { return (n + 127) / 128; };

    freqs_kernel<<<S_, 32>>>(p_cos, p_sin);

    // input conversions
    convert_split_kernel<<<cvblocks((long long)M_ * H_), 256>>>(hs, hs_h, hs_l, (long long)M_ * H_);
    convert_split_kernel<<<cvblocks((long long)QLORA * H_), 256>>>(wq_a, wqa_h, wqa_l, (long long)QLORA * H_);
    convert_split_kernel<<<cvblocks((long long)NH_ * DQK * QLORA), 256>>>(wq_b, wqb_h, wqb_l, (long long)NH_ * DQK * QLORA);
    convert_split_kernel<<<cvblocks((long long)(KVLORA + DROPE) * H_), 256>>>(wkv_a, wkva_h, wkva_l, (long long)(KVLORA + DROPE) * H_);
    convert_split_kernel<<<cvblocks((long long)NH_ * (DNOPE + DV_) * KVLORA), 256>>>(wkv_b, wkvb_h, wkvb_l, (long long)NH_ * (DNOPE + DV_) * KVLORA);
    convert_split_kernel<<<cvblocks((long long)H_ * NH_ * DV_), 256>>>(wo, wo_h, wo_l, (long long)H_ * NH_ * DV_);

    // q_a = hs @ wq_a^T   [4096 x 1536] K=2048
    hgemm<true><<<dim3(ntiles(QLORA), M_ / 128, 1), 256, GEMM_SMEM>>>(
        hs_h, hs_l, wqa_h, wqa_l, p_qa, QLORA, H_, H_, H_, QLORA,
        0, 0, 0, 0, 0, 0, 1, 1.f);

    rmsnorm_split_kernel<<<M_, 256>>>(p_qa, QLORA, q_norm_w, qa_h, qa_l, QLORA, QLORA);

    // q = q_a @ wq_b^T    [4096 x 3072] K=1536
    hgemm<true><<<dim3(ntiles(NH_ * DQK), M_ / 128, 1), 256, GEMM_SMEM>>>(
        qa_h, qa_l, wqb_h, wqb_l, p_q, NH_ * DQK, QLORA, QLORA, QLORA, NH_ * DQK,
        0, 0, 0, 0, 0, 0, 1, 1.f);

    // kv = hs @ wkv_a^T   [4096 x 576] K=2048
    hgemm<true><<<dim3(ntiles(KVLORA + DROPE), M_ / 128, 1), 256, GEMM_SMEM>>>(
        hs_h, hs_l, wkva_h, wkva_l, p_kv, KVLORA + DROPE, H_, H_, H_, KVLORA + DROPE,
        0, 0, 0, 0, 0, 0, 1, 1.f);

    rmsnorm_split_kernel<<<M_, 256>>>(p_kv, KVLORA + DROPE, kv_norm_w, kvc_h, kvc_l, KVLORA, KVLORA);
    rope_k_kernel<<<M_, 32>>>(p_kv, p_kpe, p_cos, p_sin);

    // kv_x = kv_c @ wkv_b^T  [4096 x 4096] K=512
    hgemm<true><<<dim3(ntiles(NH_ * (DNOPE + DV_)), M_ / 128, 1), 256, GEMM_SMEM>>>(
        kvc_h, kvc_l, wkvb_h, wkvb_l, p_kvx, NH_ * (DNOPE + DV_), KVLORA, KVLORA, KVLORA,
        NH_ * (DNOPE + DV_), 0, 0, 0, 0, 0, 0, 1, 1.f);

    rope_q_kernel<<<M_, 512>>>(p_q, p_cos, p_sin);
    convert_split_kernel<<<cvblocks((long long)M_ * NH_ * DQK), 256>>>(p_q, q_h, q_l, (long long)M_ * NH_ * DQK);
    build_kf_kernel<<<cvblocks((long long)M_ * NH_ * DQK), 256>>>(p_kvx, p_kpe, kf_h, kf_l);
    transpose_v_kernel<<<dim3(S_ / 32, DV_ / 32, B_ * NH_), 256>>>(p_kvx, vt_h, vt_l);

    // scores[z] = scale * Q_z @ Kf_z^T   [2048 x 2048] K=192
    hgemm<true><<<dim3(ntiles(S_), S_ / 128, B_ * NH_), 256, GEMM_SMEM>>>(
        q_h, q_l, kf_h, kf_l, p_sc, S_, DQK,
        NH_ * DQK, NH_ * DQK, S_,
        (long long)S_ * NH_ * DQK, (long long)DQK,
        (long long)S_ * NH_ * DQK, (long long)DQK,
        (long long)NH_ * S_ * S_, (long long)S_ * S_,
        NH_, scale);

    softmax_kernel<<<dim3(S_, B_ * NH_), 256>>>(p_sc, at_h);

    // ao[z] = attn_z @ Vt_z^T  [2048 x 128] K=2048 ; probs plain fp16, V split
    hgemm<false><<<dim3(1, S_ / 128, B_ * NH_), 256, GEMM_SMEM>>>(
        at_h, at_h, vt_h, vt_l, p_ao, DV_, S_,
        S_, S_, NH_ * DV_,
        (long long)NH_ * S_ * S_, (long long)S_ * S_,
        (long long)NH_ * DV_ * S_, (long long)DV_ * S_,
        (long long)S_ * NH_ * DV_, (long long)DV_,
        NH_, 1.f);

    convert_split_kernel<<<cvblocks((long long)M_ * NH_ * DV_), 256>>>(p_ao, ao_h, ao_l, (long long)M_ * NH_ * DV_);

    // out = ao @ wo^T   [4096 x 2048] K=2048
    hgemm<true><<<dim3(ntiles(H_), M_ / 128, 1), 256, GEMM_SMEM>>>(
        ao_h, ao_l, wo_h, wo_l, out, H_, NH_ * DV_, NH_ * DV_, NH_ * DV_, H_,
        0, 0, 0, 0, 0, 0, 1, 1.f);
}

// round 9
// speedup vs baseline: 3.4799x; 1.2015x over previous
#include <cuda_runtime.h>
#include <cuda_fp16.h>
#include <math.h>
#include <stdint.h>

// ---------------- problem constants ----------------
#define B_    2
#define S_    2048
#define H_    2048
#define NH_   16
#define QLORA 1536
#define KVLORA 512
#define DNOPE 128
#define DROPE 64
#define DV_   128
#define DQK   192
#define M_    (B_ * S_)    // 4096

// ---------------- fp32 scratch ----------------
__device__ __align__(16) float g_qa  [(size_t)M_ * QLORA];
__device__ __align__(16) float g_q   [(size_t)M_ * (NH_ * DQK)];
__device__ __align__(16) float g_kv  [(size_t)M_ * (KVLORA + DROPE)];
__device__ __align__(16) float g_kpe [(size_t)M_ * DROPE];
__device__ __align__(16) float g_kvx [(size_t)M_ * (NH_ * (DNOPE + DV_))];
__device__ __align__(16) float g_sc  [(size_t)B_ * NH_ * S_ * S_];   // 536 MB
__device__ __align__(16) float g_ao  [(size_t)M_ * (NH_ * DV_)];
__device__ float g_cos [S_ * (DROPE / 2)];
__device__ float g_sin [S_ * (DROPE / 2)];

// ---------------- fp16 operand buffers ----------------
// Activations (A operands): hi only. Weights / kf / vt (B operands): hi+lo split.
__device__ __align__(16) __half g_hs_h [(size_t)M_ * H_];
__device__ __align__(16) __half g_wqa_h[(size_t)QLORA * H_],         g_wqa_l[(size_t)QLORA * H_];
__device__ __align__(16) __half g_wqb_h[(size_t)NH_ * DQK * QLORA],  g_wqb_l[(size_t)NH_ * DQK * QLORA];
__device__ __align__(16) __half g_wkva_h[(size_t)(KVLORA + DROPE) * H_], g_wkva_l[(size_t)(KVLORA + DROPE) * H_];
__device__ __align__(16) __half g_wkvb_h[(size_t)NH_ * (DNOPE + DV_) * KVLORA], g_wkvb_l[(size_t)NH_ * (DNOPE + DV_) * KVLORA];
__device__ __align__(16) __half g_wo_h [(size_t)H_ * NH_ * DV_],     g_wo_l [(size_t)H_ * NH_ * DV_];
__device__ __align__(16) __half g_qa_h [(size_t)M_ * QLORA];
__device__ __align__(16) __half g_qh   [(size_t)M_ * NH_ * DQK];
__device__ __align__(16) __half g_kvc_h[(size_t)M_ * KVLORA];
__device__ __align__(16) __half g_kf_h [(size_t)M_ * NH_ * DQK],     g_kf_l [(size_t)M_ * NH_ * DQK];
__device__ __align__(16) __half g_vt_h [(size_t)B_ * NH_ * DV_ * S_], g_vt_l [(size_t)B_ * NH_ * DV_ * S_];
__device__ __align__(16) __half g_at_h [(size_t)B_ * NH_ * S_ * S_];  // probs (268 MB)
__device__ __align__(16) __half g_ao_h [(size_t)M_ * NH_ * DV_];

// ---------------- helpers ----------------
__device__ __forceinline__ void split_write(float v, __half* ph, __half* pl) {
    __half h = __float2half_rn(v);
    *ph = h;
    *pl = __float2half_rn(v - __half2float(h));
}

__device__ __forceinline__ uint32_t smem_u32(const void* p) {
    uint32_t a;
    asm("{ .reg .u64 t; cvta.to.shared.u64 t, %1; cvt.u32.u64 %0, t; }" : "=r"(a) : "l"(p));
    return a;
}

__device__ __forceinline__ void cp16(uint32_t dst, const void* src, bool pred) {
    int sz = pred ? 16 : 0;
    asm volatile("cp.async.cg.shared.global [%0], [%1], 16, %2;\n"
                 :: "r"(dst), "l"(src), "r"(sz));
}
#define CP_COMMIT()   asm volatile("cp.async.commit_group;\n" ::: "memory")
#define CP_WAIT(n)    asm volatile("cp.async.wait_group %0;\n" :: "n"(n) : "memory")

__device__ __forceinline__ void mma_fp16(float* c, const uint32_t* a, const uint32_t* b) {
    asm volatile(
        "mma.sync.aligned.m16n8k16.row.col.f32.f16.f16.f32 "
        "{%0,%1,%2,%3}, {%4,%5,%6,%7}, {%8,%9}, {%0,%1,%2,%3};\n"
        : "+f"(c[0]), "+f"(c[1]), "+f"(c[2]), "+f"(c[3])
        : "r"(a[0]), "r"(a[1]), "r"(a[2]), "r"(a[3]), "r"(b[0]), "r"(b[1]));
}

__device__ __forceinline__ void ldsm_x4(uint32_t* r, uint32_t addr) {
    asm volatile("ldmatrix.sync.aligned.m8n8.x4.shared.b16 {%0,%1,%2,%3}, [%4];"
        : "=r"(r[0]), "=r"(r[1]), "=r"(r[2]), "=r"(r[3]) : "r"(addr));
}

// ---------------- pipelined fp16 tensor-core GEMM (A plain, B split) ----------------
// C[m,n] = alpha * sum_k A[m,k] * B[n,k]   (B row-major [n][k], K-contiguous)
// B = Bh + Bl (fp16 hi/lo): 2 MMAs per logical (A*Bh + A*Bl).
// Tile 128x128, K-chunk 32, 3-stage cp.async pipeline, 256 thr, 2 CTA/SM.
// smem per stage: A(10240) Bh(10240) Bl(10240) ; row stride 40 halves (80B)
#define STG_A   0
#define STG_B_H 10240
#define STG_B_L 20480
#define STG_BYTES 30720
#define GEMM_SMEM (3 * STG_BYTES)

extern __shared__ char sm_raw[];

__global__ void __launch_bounds__(256, 2)
hgemm(const __half* __restrict__ A,
      const __half* __restrict__ Bh, const __half* __restrict__ Bl,
      float* __restrict__ C,
      int N, int K, int lda, int ldb, int ldc,
      long long sAb, long long sAhh, long long sBb, long long sBhh,
      long long sCb, long long sChh, int nh, float alpha)
{
    const int z = blockIdx.z;
    const int bb = z / nh, hh = z % nh;
    A  += bb * sAb + hh * sAhh;
    Bh += bb * sBb + hh * sBhh;  Bl += bb * sBb + hh * sBhh;
    C  += bb * sCb + hh * sChh;

    const int tid = threadIdx.x;
    const int lane = tid & 31, w = tid >> 5;
    const int wm = (w >> 1) * 32, wn = (w & 1) * 64;
    const int m0 = blockIdx.y * 128, n0 = blockIdx.x * 128;
    const int fr = lane >> 2, fc = (lane & 3) * 2;
    const int nk = K >> 5;                 // K multiple of 32 at all call sites

    const uint32_t smem = smem_u32(sm_raw);

    // ---- ldmatrix per-lane byte offsets (within stage regions) ----
    uint32_t aoff[2], boff[4];
    {
        int r = wm + (lane & 15);
        int c = (lane >> 4) * 8;
        aoff[0] = (uint32_t)((r * 40 + c) * 2);
        aoff[1] = (uint32_t)(((r + 16) * 40 + c) * 2);
        int lnB = lane & 7;
        int pHi = lane >> 4;              // which nt within the pair
        int kh  = ((lane >> 3) & 1) * 8;  // k half
#pragma unroll
        for (int p = 0; p < 4; p++) {
            int n = wn + (2 * p + pHi) * 8 + lnB;
            boff[p] = (uint32_t)((n * 40 + kh) * 2);
        }
    }

    // loader: thread handles rows (tid>>2, +64) chunk (tid&3)
    const int lrow0 = tid >> 2, lch = tid & 3;
    const __half* gA  = A + (long long)(m0 + lrow0) * lda + lch * 8;
    const __half* gA2 = gA + 64ll * lda;
    const bool bp1 = (n0 + lrow0) < N;
    const bool bp2 = (n0 + lrow0 + 64) < N;
    const __half* gB_h  = Bh + (long long)(n0 + (bp1 ? lrow0 : 0)) * ldb + lch * 8;
    const __half* gB_l  = Bl + (long long)(n0 + (bp1 ? lrow0 : 0)) * ldb + lch * 8;
    const __half* gB_h2 = Bh + (long long)(n0 + (bp2 ? lrow0 + 64 : 0)) * ldb + lch * 8;
    const __half* gB_l2 = Bl + (long long)(n0 + (bp2 ? lrow0 + 64 : 0)) * ldb + lch * 8;
    const uint32_t so1 = (uint32_t)(lrow0 * 80 + lch * 16);
    const uint32_t so2 = (uint32_t)((lrow0 + 64) * 80 + lch * 16);

    auto load_stage = [&](int kc, int st) {
        uint32_t sb = smem + st * STG_BYTES;
        cp16(sb + STG_A + so1, gA  + kc, true);
        cp16(sb + STG_A + so2, gA2 + kc, true);
        cp16(sb + STG_B_H + so1, gB_h  + kc, bp1);
        cp16(sb + STG_B_H + so2, gB_h2 + kc, bp2);
        cp16(sb + STG_B_L + so1, gB_l  + kc, bp1);
        cp16(sb + STG_B_L + so2, gB_l2 + kc, bp2);
        CP_COMMIT();
    };

    float acc[2][8][4] = {};

    // 3-stage prologue
    load_stage(0, 0);
    if (nk > 1) load_stage(32, 1); else CP_COMMIT();

    for (int k = 0; k < nk; k++) {
        const int st = k % 3;
        if (k + 2 < nk) load_stage((k + 2) * 32, (k + 2) % 3);
        else CP_COMMIT();
        CP_WAIT(2);
        __syncthreads();

        const uint32_t sb = smem + st * STG_BYTES;

#pragma unroll
        for (int ks = 0; ks < 2; ks++) {
            const uint32_t kB = ks * 32;   // 16 halves = 32 bytes
            uint32_t a[2][4];
#pragma unroll
            for (int mt = 0; mt < 2; mt++)
                ldsm_x4(a[mt], sb + STG_A + aoff[mt] + kB);
#pragma unroll
            for (int p = 0; p < 4; p++) {
                uint32_t bh[4], bl[4];
                ldsm_x4(bh, sb + STG_B_H + boff[p] + kB);
                ldsm_x4(bl, sb + STG_B_L + boff[p] + kB);
#pragma unroll
                for (int sub = 0; sub < 2; sub++) {
                    const uint32_t* bph = bh + 2 * sub;
                    const uint32_t* bpl = bl + 2 * sub;
                    const int nt = 2 * p + sub;
#pragma unroll
                    for (int mt = 0; mt < 2; mt++) {
                        mma_fp16(acc[mt][nt], a[mt], bph);
                        mma_fp16(acc[mt][nt], a[mt], bpl);
                    }
                }
            }
        }
        __syncthreads();
    }

    // epilogue
#pragma unroll
    for (int mt = 0; mt < 2; mt++) {
        int row = m0 + wm + mt * 16 + fr;
#pragma unroll
        for (int nt = 0; nt < 8; nt++) {
            int col = n0 + wn + nt * 8 + fc;
            if (col < N) {
                C[(long long)row * ldc + col]           = alpha * acc[mt][nt][0];
                C[(long long)row * ldc + col + 1]       = alpha * acc[mt][nt][1];
                C[(long long)(row + 8) * ldc + col]     = alpha * acc[mt][nt][2];
                C[(long long)(row + 8) * ldc + col + 1] = alpha * acc[mt][nt][3];
            }
        }
    }
}

// ---------------- fp32 -> fp16 (hi only) ----------------
__global__ void convert_h_kernel(const float* __restrict__ x,
                                 __half* __restrict__ h, long long n)
{
    long long i = (long long)blockIdx.x * 256 + threadIdx.x;
    if (i < n) h[i] = __float2half_rn(x[i]);
}

// ---------------- fp32 -> (hi,lo) fp16 convert ----------------
__global__ void convert_split_kernel(const float* __restrict__ x,
                                     __half* __restrict__ h,
                                     __half* __restrict__ l, long long n)
{
    long long i = (long long)blockIdx.x * 256 + threadIdx.x;
    if (i < n) split_write(x[i], h + i, l + i);
}

// ---------------- RMSNorm -> fp16 hi ----------------
__global__ void __launch_bounds__(256)
rmsnorm_h_kernel(const float* __restrict__ x, int ldx, const float* __restrict__ w,
                 __half* __restrict__ yh, int ldy, int cols)
{
    const int row = blockIdx.x;
    const float* xr = x + (long long)row * ldx;
    float ss = 0.f;
    for (int c = threadIdx.x; c < cols; c += 256) { float v = xr[c]; ss += v * v; }
    __shared__ float red[256];
    red[threadIdx.x] = ss;
    __syncthreads();
    for (int s = 128; s > 0; s >>= 1) {
        if (threadIdx.x < s) red[threadIdx.x] += red[threadIdx.x + s];
        __syncthreads();
    }
    float inv = 1.f / sqrtf(red[0] / (float)cols + 1e-6f);
    long long base = (long long)row * ldy;
    for (int c = threadIdx.x; c < cols; c += 256)
        yh[base + c] = __float2half_rn(w[c] * xr[c] * inv);
}

// ---------------- RoPE ----------------
__global__ void freqs_kernel(float* __restrict__ cosd, float* __restrict__ sind)
{
    int t = blockIdx.x, i = threadIdx.x;
    double inv = pow(10000.0, -(double)(2 * i) / (double)DROPE);
    double f = (double)t * inv;
    cosd[t * 32 + i] = (float)cos(f);
    sind[t * 32 + i] = (float)sin(f);
}

__global__ void __launch_bounds__(512)
rope_q_kernel(float* __restrict__ q, const float* __restrict__ cosd,
              const float* __restrict__ sind)
{
    int m = blockIdx.x;
    int t = m & (S_ - 1);
    int h = threadIdx.x >> 5, i = threadIdx.x & 31;
    float cs = cosd[t * 32 + i], sn = sind[t * 32 + i];
    long long base = (long long)m * (NH_ * DQK) + h * DQK + DNOPE + 2 * i;
    float e = q[base], o = q[base + 1];
    q[base]     = e * cs - o * sn;
    q[base + 1] = e * sn + o * cs;
}

__global__ void rope_k_kernel(const float* __restrict__ kv, float* __restrict__ kpe,
                              const float* __restrict__ cosd, const float* __restrict__ sind)
{
    int m = blockIdx.x;
    int t = m & (S_ - 1);
    int i = threadIdx.x;
    float cs = cosd[t * 32 + i], sn = sind[t * 32 + i];
    long long base = (long long)m * (KVLORA + DROPE) + KVLORA + 2 * i;
    float e = kv[base], o = kv[base + 1];
    kpe[m * DROPE + 2 * i]     = e * cs - o * sn;
    kpe[m * DROPE + 2 * i + 1] = e * sn + o * cs;
}

// ---------------- kf assembly (split fp16; B operand of scores) ----------------
__global__ void build_kf_kernel(const float* __restrict__ kvx, const float* __restrict__ kpe,
                                __half* __restrict__ kfh, __half* __restrict__ kfl)
{
    long long idx = (long long)blockIdx.x * 256 + threadIdx.x;
    int col = (int)(idx % (NH_ * DQK));
    long long m = idx / (NH_ * DQK);
    int h = col / DQK, d = col % DQK;
    float v;
    if (d < DNOPE) v = kvx[m * (NH_ * (DNOPE + DV_)) + h * (DNOPE + DV_) + d];
    else           v = kpe[m * DROPE + (d - DNOPE)];
    split_write(v, kfh + idx, kfl + idx);
}

// ---------------- V extraction + transpose: vt[b][h][d][s] (split; B of attnV) ----------------
__global__ void __launch_bounds__(256)
transpose_v_kernel(const float* __restrict__ kvx,
                   __half* __restrict__ vth, __half* __restrict__ vtl)
{
    __shared__ float t[32][33];
    int z = blockIdx.z;
    int b = z / NH_, h = z % NH_;
    int s0 = blockIdx.x * 32, d0 = blockIdx.y * 32;
    int tx = threadIdx.x & 31, ty = threadIdx.x >> 5;
#pragma unroll
    for (int i = ty; i < 32; i += 8)
        t[i][tx] = kvx[((long long)(b * S_ + s0 + i)) * (NH_ * (DNOPE + DV_))
                       + h * (DNOPE + DV_) + DNOPE + d0 + tx];
    __syncthreads();
#pragma unroll
    for (int i = ty; i < 32; i += 8) {
        long long o = ((long long)z * DV_ + d0 + i) * S_ + s0 + tx;
        split_write(t[tx][i], vth + o, vtl + o);
    }
}

// ---------------- softmax -> fp16 (hi only) ----------------
__global__ void __launch_bounds__(256)
softmax_kernel(const float* __restrict__ s, __half* __restrict__ ah)
{
    long long off = ((long long)blockIdx.y * S_ + blockIdx.x) * (long long)S_;
    const float* row = s + off;
    __shared__ float red[256];
    float mx = -1e30f;
    for (int c = threadIdx.x; c < S_; c += 256) mx = fmaxf(mx, row[c]);
    red[threadIdx.x] = mx;
    __syncthreads();
    for (int st = 128; st > 0; st >>= 1) {
        if (threadIdx.x < st) red[threadIdx.x] = fmaxf(red[threadIdx.x], red[threadIdx.x + st]);
        __syncthreads();
    }
    mx = red[0];
    __syncthreads();
    float sum = 0.f;
    for (int c = threadIdx.x; c < S_; c += 256) sum += __expf(row[c] - mx);
    red[threadIdx.x] = sum;
    __syncthreads();
    for (int st = 128; st > 0; st >>= 1) {
        if (threadIdx.x < st) red[threadIdx.x] += red[threadIdx.x + st];
        __syncthreads();
    }
    float inv = 1.f / red[0];
    for (int c = threadIdx.x; c < S_; c += 256)
        ah[off + c] = __float2half_rn(__expf(row[c] - mx) * inv);
}

// ---------------- launch ----------------
extern "C" void kernel_launch(void* const* d_in, const int* in_sizes, int n_in,
                              void* d_out, int out_size)
{
    const float* hs        = (const float*)d_in[0];
    const float* wq_a      = (const float*)d_in[1];
    const float* q_norm_w  = (const float*)d_in[2];
    const float* wq_b      = (const float*)d_in[3];
    const float* wkv_a     = (const float*)d_in[4];
    const float* kv_norm_w = (const float*)d_in[5];
    const float* wkv_b     = (const float*)d_in[6];
    const float* wo        = (const float*)d_in[7];
    float* out = (float*)d_out;

    cudaFuncSetAttribute(hgemm, cudaFuncAttributeMaxDynamicSharedMemorySize, GEMM_SMEM);

    float *p_qa, *p_q, *p_kv, *p_kpe, *p_kvx, *p_sc, *p_ao, *p_cos, *p_sin;
    cudaGetSymbolAddress((void**)&p_qa,  g_qa);
    cudaGetSymbolAddress((void**)&p_q,   g_q);
    cudaGetSymbolAddress((void**)&p_kv,  g_kv);
    cudaGetSymbolAddress((void**)&p_kpe, g_kpe);
    cudaGetSymbolAddress((void**)&p_kvx, g_kvx);
    cudaGetSymbolAddress((void**)&p_sc,  g_sc);
    cudaGetSymbolAddress((void**)&p_ao,  g_ao);
    cudaGetSymbolAddress((void**)&p_cos, g_cos);
    cudaGetSymbolAddress((void**)&p_sin, g_sin);

    __half *hs_h, *wqa_h, *wqa_l, *wqb_h, *wqb_l, *wkva_h, *wkva_l;
    __half *wkvb_h, *wkvb_l, *wo_h, *wo_l, *qa_h, *q_h;
    __half *kvc_h, *kf_h, *kf_l, *vt_h, *vt_l, *at_h, *ao_h;
    cudaGetSymbolAddress((void**)&hs_h,  g_hs_h);
    cudaGetSymbolAddress((void**)&wqa_h, g_wqa_h);  cudaGetSymbolAddress((void**)&wqa_l, g_wqa_l);
    cudaGetSymbolAddress((void**)&wqb_h, g_wqb_h);  cudaGetSymbolAddress((void**)&wqb_l, g_wqb_l);
    cudaGetSymbolAddress((void**)&wkva_h, g_wkva_h); cudaGetSymbolAddress((void**)&wkva_l, g_wkva_l);
    cudaGetSymbolAddress((void**)&wkvb_h, g_wkvb_h); cudaGetSymbolAddress((void**)&wkvb_l, g_wkvb_l);
    cudaGetSymbolAddress((void**)&wo_h,  g_wo_h);   cudaGetSymbolAddress((void**)&wo_l,  g_wo_l);
    cudaGetSymbolAddress((void**)&qa_h,  g_qa_h);
    cudaGetSymbolAddress((void**)&q_h,   g_qh);
    cudaGetSymbolAddress((void**)&kvc_h, g_kvc_h);
    cudaGetSymbolAddress((void**)&kf_h,  g_kf_h);   cudaGetSymbolAddress((void**)&kf_l,  g_kf_l);
    cudaGetSymbolAddress((void**)&vt_h,  g_vt_h);   cudaGetSymbolAddress((void**)&vt_l,  g_vt_l);
    cudaGetSymbolAddress((void**)&at_h,  g_at_h);
    cudaGetSymbolAddress((void**)&ao_h,  g_ao_h);

    const float scale = 1.0f / sqrtf((float)DQK);
    auto cvblocks = [](long long n) { return (int)((n + 255) / 256); };
    auto ntiles = [](int n) { return (n + 127) / 128; };

    freqs_kernel<<<S_, 32>>>(p_cos, p_sin);

    // input conversions: activations hi-only, weights split
    convert_h_kernel<<<cvblocks((long long)M_ * H_), 256>>>(hs, hs_h, (long long)M_ * H_);
    convert_split_kernel<<<cvblocks((long long)QLORA * H_), 256>>>(wq_a, wqa_h, wqa_l, (long long)QLORA * H_);
    convert_split_kernel<<<cvblocks((long long)NH_ * DQK * QLORA), 256>>>(wq_b, wqb_h, wqb_l, (long long)NH_ * DQK * QLORA);
    convert_split_kernel<<<cvblocks((long long)(KVLORA + DROPE) * H_), 256>>>(wkv_a, wkva_h, wkva_l, (long long)(KVLORA + DROPE) * H_);
    convert_split_kernel<<<cvblocks((long long)NH_ * (DNOPE + DV_) * KVLORA), 256>>>(wkv_b, wkvb_h, wkvb_l, (long long)NH_ * (DNOPE + DV_) * KVLORA);
    convert_split_kernel<<<cvblocks((long long)H_ * NH_ * DV_), 256>>>(wo, wo_h, wo_l, (long long)H_ * NH_ * DV_);

    // q_a = hs @ wq_a^T   [4096 x 1536] K=2048
    hgemm<<<dim3(ntiles(QLORA), M_ / 128, 1), 256, GEMM_SMEM>>>(
        hs_h, wqa_h, wqa_l, p_qa, QLORA, H_, H_, H_, QLORA,
        0, 0, 0, 0, 0, 0, 1, 1.f);

    rmsnorm_h_kernel<<<M_, 256>>>(p_qa, QLORA, q_norm_w, qa_h, QLORA, QLORA);

    // q = q_a @ wq_b^T    [4096 x 3072] K=1536
    hgemm<<<dim3(ntiles(NH_ * DQK), M_ / 128, 1), 256, GEMM_SMEM>>>(
        qa_h, wqb_h, wqb_l, p_q, NH_ * DQK, QLORA, QLORA, QLORA, NH_ * DQK,
        0, 0, 0, 0, 0, 0, 1, 1.f);

    // kv = hs @ wkv_a^T   [4096 x 576] K=2048
    hgemm<<<dim3(ntiles(KVLORA + DROPE), M_ / 128, 1), 256, GEMM_SMEM>>>(
        hs_h, wkva_h, wkva_l, p_kv, KVLORA + DROPE, H_, H_, H_, KVLORA + DROPE,
        0, 0, 0, 0, 0, 0, 1, 1.f);

    rmsnorm_h_kernel<<<M_, 256>>>(p_kv, KVLORA + DROPE, kv_norm_w, kvc_h, KVLORA, KVLORA);
    rope_k_kernel<<<M_, 32>>>(p_kv, p_kpe, p_cos, p_sin);

    // kv_x = kv_c @ wkv_b^T  [4096 x 4096] K=512
    hgemm<<<dim3(ntiles(NH_ * (DNOPE + DV_)), M_ / 128, 1), 256, GEMM_SMEM>>>(
        kvc_h, wkvb_h, wkvb_l, p_kvx, NH_ * (DNOPE + DV_), KVLORA, KVLORA, KVLORA,
        NH_ * (DNOPE + DV_), 0, 0, 0, 0, 0, 0, 1, 1.f);

    rope_q_kernel<<<M_, 512>>>(p_q, p_cos, p_sin);
    convert_h_kernel<<<cvblocks((long long)M_ * NH_ * DQK), 256>>>(p_q, q_h, (long long)M_ * NH_ * DQK);
    build_kf_kernel<<<cvblocks((long long)M_ * NH_ * DQK), 256>>>(p_kvx, p_kpe, kf_h, kf_l);
    transpose_v_kernel<<<dim3(S_ / 32, DV_ / 32, B_ * NH_), 256>>>(p_kvx, vt_h, vt_l);

    // scores[z] = scale * Q_z @ Kf_z^T   [2048 x 2048] K=192
    hgemm<<<dim3(ntiles(S_), S_ / 128, B_ * NH_), 256, GEMM_SMEM>>>(
        q_h, kf_h, kf_l, p_sc, S_, DQK,
        NH_ * DQK, NH_ * DQK, S_,
        (long long)S_ * NH_ * DQK, (long long)DQK,
        (long long)S_ * NH_ * DQK, (long long)DQK,
        (long long)NH_ * S_ * S_, (long long)S_ * S_,
        NH_, scale);

    softmax_kernel<<<dim3(S_, B_ * NH_), 256>>>(p_sc, at_h);

    // ao[z] = attn_z @ Vt_z^T  [2048 x 128] K=2048
    hgemm<<<dim3(1, S_ / 128, B_ * NH_), 256, GEMM_SMEM>>>(
        at_h, vt_h, vt_l, p_ao, DV_, S_,
        S_, S_, NH_ * DV_,
        (long long)NH_ * S_ * S_, (long long)S_ * S_,
        (long long)NH_ * DV_ * S_, (long long)DV_ * S_,
        (long long)S_ * NH_ * DV_, (long long)DV_,
        NH_, 1.f);

    convert_h_kernel<<<cvblocks((long long)M_ * NH_ * DV_), 256>>>(p_ao, ao_h, (long long)M_ * NH_ * DV_);

    // out = ao @ wo^T   [4096 x 2048] K=2048
    hgemm<<<dim3(ntiles(H_), M_ / 128, 1), 256, GEMM_SMEM>>>(
        ao_h, wo_h, wo_l, out, H_, NH_ * DV_, NH_ * DV_, NH_ * DV_, H_,
        0, 0, 0, 0, 0, 0, 1, 1.f);
}

// round 11
// speedup vs baseline: 4.4416x; 1.2763x over previous
#include <cuda_runtime.h>
#include <cuda_fp16.h>
#include <math.h>
#include <stdint.h>

// ---------------- problem constants ----------------
#define B_    2
#define S_    2048
#define H_    2048
#define NH_   16
#define QLORA 1536
#define KVLORA 512
#define DNOPE 128
#define DROPE 64
#define DV_   128
#define DQK   192
#define M_    (B_ * S_)    // 4096

// ---------------- fp32 scratch ----------------
__device__ __align__(16) float g_qa  [(size_t)M_ * QLORA];
__device__ __align__(16) float g_q   [(size_t)M_ * (NH_ * DQK)];
__device__ __align__(16) float g_kv  [(size_t)M_ * (KVLORA + DROPE)];
__device__ __align__(16) float g_kpe [(size_t)M_ * DROPE];
__device__ __align__(16) float g_kvx [(size_t)M_ * (NH_ * (DNOPE + DV_))];
__device__ float g_cos [S_ * (DROPE / 2)];
__device__ float g_sin [S_ * (DROPE / 2)];

// ---------------- fp16 operand buffers ----------------
__device__ __align__(16) __half g_hs_h [(size_t)M_ * H_];
__device__ __align__(16) __half g_wqa_h[(size_t)QLORA * H_],         g_wqa_l[(size_t)QLORA * H_];
__device__ __align__(16) __half g_wqb_h[(size_t)NH_ * DQK * QLORA],  g_wqb_l[(size_t)NH_ * DQK * QLORA];
__device__ __align__(16) __half g_wkva_h[(size_t)(KVLORA + DROPE) * H_], g_wkva_l[(size_t)(KVLORA + DROPE) * H_];
__device__ __align__(16) __half g_wkvb_h[(size_t)NH_ * (DNOPE + DV_) * KVLORA], g_wkvb_l[(size_t)NH_ * (DNOPE + DV_) * KVLORA];
__device__ __align__(16) __half g_wo_h [(size_t)H_ * NH_ * DV_],     g_wo_l [(size_t)H_ * NH_ * DV_];
__device__ __align__(16) __half g_qa_h [(size_t)M_ * QLORA];
__device__ __align__(16) __half g_qh   [(size_t)M_ * NH_ * DQK];
__device__ __align__(16) __half g_kvc_h[(size_t)M_ * KVLORA];
__device__ __align__(16) __half g_kf_h [(size_t)M_ * NH_ * DQK],     g_kf_l [(size_t)M_ * NH_ * DQK];
__device__ __align__(16) __half g_vt_h [(size_t)B_ * NH_ * DV_ * S_], g_vt_l [(size_t)B_ * NH_ * DV_ * S_];
__device__ __align__(16) __half g_ao_h [(size_t)M_ * NH_ * DV_];

// ---------------- helpers ----------------
__device__ __forceinline__ void split_write(float v, __half* ph, __half* pl) {
    __half h = __float2half_rn(v);
    *ph = h;
    *pl = __float2half_rn(v - __half2float(h));
}

__device__ __forceinline__ uint32_t smem_u32(const void* p) {
    uint32_t a;
    asm("{ .reg .u64 t; cvta.to.shared.u64 t, %1; cvt.u32.u64 %0, t; }" : "=r"(a) : "l"(p));
    return a;
}

__device__ __forceinline__ void cp16(uint32_t dst, const void* src, bool pred) {
    int sz = pred ? 16 : 0;
    asm volatile("cp.async.cg.shared.global [%0], [%1], 16, %2;\n"
                 :: "r"(dst), "l"(src), "r"(sz));
}
#define CP_COMMIT()   asm volatile("cp.async.commit_group;\n" ::: "memory")
#define CP_WAIT(n)    asm volatile("cp.async.wait_group %0;\n" :: "n"(n) : "memory")

__device__ __forceinline__ void mma_fp16(float* c, const uint32_t* a, const uint32_t* b) {
    asm volatile(
        "mma.sync.aligned.m16n8k16.row.col.f32.f16.f16.f32 "
        "{%0,%1,%2,%3}, {%4,%5,%6,%7}, {%8,%9}, {%0,%1,%2,%3};\n"
        : "+f"(c[0]), "+f"(c[1]), "+f"(c[2]), "+f"(c[3])
        : "r"(a[0]), "r"(a[1]), "r"(a[2]), "r"(a[3]), "r"(b[0]), "r"(b[1]));
}

__device__ __forceinline__ void ldsm_x4(uint32_t* r, uint32_t addr) {
    asm volatile("ldmatrix.sync.aligned.m8n8.x4.shared.b16 {%0,%1,%2,%3}, [%4];"
        : "=r"(r[0]), "=r"(r[1]), "=r"(r[2]), "=r"(r[3]) : "r"(addr));
}

// ---------------- pipelined fp16 tensor-core GEMM (A plain, B split) ----------------
#define STG_A   0
#define STG_B_H 10240
#define STG_B_L 20480
#define STG_BYTES 30720
#define GEMM_SMEM (3 * STG_BYTES)

extern __shared__ char sm_raw[];

__global__ void __launch_bounds__(256, 2)
hgemm(const __half* __restrict__ A,
      const __half* __restrict__ Bh, const __half* __restrict__ Bl,
      float* __restrict__ C,
      int N, int K, int lda, int ldb, int ldc,
      long long sAb, long long sAhh, long long sBb, long long sBhh,
      long long sCb, long long sChh, int nh, float alpha)
{
    const int z = blockIdx.z;
    const int bb = z / nh, hh = z % nh;
    A  += bb * sAb + hh * sAhh;
    Bh += bb * sBb + hh * sBhh;  Bl += bb * sBb + hh * sBhh;
    C  += bb * sCb + hh * sChh;

    const int tid = threadIdx.x;
    const int lane = tid & 31, w = tid >> 5;
    const int wm = (w >> 1) * 32, wn = (w & 1) * 64;
    const int m0 = blockIdx.y * 128, n0 = blockIdx.x * 128;
    const int fr = lane >> 2, fc = (lane & 3) * 2;
    const int nk = K >> 5;

    const uint32_t smem = smem_u32(sm_raw);

    uint32_t aoff[2], boff[4];
    {
        int r = wm + (lane & 15);
        int c = (lane >> 4) * 8;
        aoff[0] = (uint32_t)((r * 40 + c) * 2);
        aoff[1] = (uint32_t)(((r + 16) * 40 + c) * 2);
        int lnB = lane & 7;
        int pHi = lane >> 4;
        int kh  = ((lane >> 3) & 1) * 8;
#pragma unroll
        for (int p = 0; p < 4; p++) {
            int n = wn + (2 * p + pHi) * 8 + lnB;
            boff[p] = (uint32_t)((n * 40 + kh) * 2);
        }
    }

    const int lrow0 = tid >> 2, lch = tid & 3;
    const __half* gA  = A + (long long)(m0 + lrow0) * lda + lch * 8;
    const __half* gA2 = gA + 64ll * lda;
    const bool bp1 = (n0 + lrow0) < N;
    const bool bp2 = (n0 + lrow0 + 64) < N;
    const __half* gB_h  = Bh + (long long)(n0 + (bp1 ? lrow0 : 0)) * ldb + lch * 8;
    const __half* gB_l  = Bl + (long long)(n0 + (bp1 ? lrow0 : 0)) * ldb + lch * 8;
    const __half* gB_h2 = Bh + (long long)(n0 + (bp2 ? lrow0 + 64 : 0)) * ldb + lch * 8;
    const __half* gB_l2 = Bl + (long long)(n0 + (bp2 ? lrow0 + 64 : 0)) * ldb + lch * 8;
    const uint32_t so1 = (uint32_t)(lrow0 * 80 + lch * 16);
    const uint32_t so2 = (uint32_t)((lrow0 + 64) * 80 + lch * 16);

    auto load_stage = [&](int kc, int st) {
        uint32_t sb = smem + st * STG_BYTES;
        cp16(sb + STG_A + so1, gA  + kc, true);
        cp16(sb + STG_A + so2, gA2 + kc, true);
        cp16(sb + STG_B_H + so1, gB_h  + kc, bp1);
        cp16(sb + STG_B_H + so2, gB_h2 + kc, bp2);
        cp16(sb + STG_B_L + so1, gB_l  + kc, bp1);
        cp16(sb + STG_B_L + so2, gB_l2 + kc, bp2);
        CP_COMMIT();
    };

    float acc[2][8][4] = {};

    load_stage(0, 0);
    if (nk > 1) load_stage(32, 1); else CP_COMMIT();

    for (int k = 0; k < nk; k++) {
        const int st = k % 3;
        if (k + 2 < nk) load_stage((k + 2) * 32, (k + 2) % 3);
        else CP_COMMIT();
        CP_WAIT(2);
        __syncthreads();

        const uint32_t sb = smem + st * STG_BYTES;

#pragma unroll
        for (int ks = 0; ks < 2; ks++) {
            const uint32_t kB = ks * 32;
            uint32_t a[2][4];
#pragma unroll
            for (int mt = 0; mt < 2; mt++)
                ldsm_x4(a[mt], sb + STG_A + aoff[mt] + kB);
#pragma unroll
            for (int p = 0; p < 4; p++) {
                uint32_t bh[4], bl[4];
                ldsm_x4(bh, sb + STG_B_H + boff[p] + kB);
                ldsm_x4(bl, sb + STG_B_L + boff[p] + kB);
#pragma unroll
                for (int sub = 0; sub < 2; sub++) {
                    const int nt = 2 * p + sub;
#pragma unroll
                    for (int mt = 0; mt < 2; mt++) {
                        mma_fp16(acc[mt][nt], a[mt], bh + 2 * sub);
                        mma_fp16(acc[mt][nt], a[mt], bl + 2 * sub);
                    }
                }
            }
        }
        __syncthreads();
    }

#pragma unroll
    for (int mt = 0; mt < 2; mt++) {
        int row = m0 + wm + mt * 16 + fr;
#pragma unroll
        for (int nt = 0; nt < 8; nt++) {
            int col = n0 + wn + nt * 8 + fc;
            if (col < N) {
                C[(long long)row * ldc + col]           = alpha * acc[mt][nt][0];
                C[(long long)row * ldc + col + 1]       = alpha * acc[mt][nt][1];
                C[(long long)(row + 8) * ldc + col]     = alpha * acc[mt][nt][2];
                C[(long long)(row + 8) * ldc + col + 1] = alpha * acc[mt][nt][3];
            }
        }
    }
}

// ---------------- fused flash attention ----------------
// Per CTA: 128 queries of one (b,h). Online softmax over 32 key blocks of 64.
// Q (fp16 hi, A operand) in smem; K split hi/lo double-buffered; V^T split hi/lo
// single-buffered; P exchanged via smem. Output: ao_h fp16 (A of final GEMM).
// smem map (halves strides: Q/K rows 200, V/P rows 72):
#define FL_Q    0                         // 128*200*2          = 51200
#define FL_K    51200                     // 2 st * (25600+25600) = 102400
#define FL_KS   51200                     // per-stage size
#define FL_KLO  25600                     // lo offset within stage
#define FL_V    153600                    // 18432 hi + 18432 lo = 36864
#define FL_VLO  18432
#define FL_P    190464                    // 128*72*2 = 18432
#define FL_RED  208896                    // 2*128 max + 2*128 sum floats = 2048
#define FL_SMEM 210944

__global__ void __launch_bounds__(256, 1)
flash_attn(const __half* __restrict__ Qg,
           const __half* __restrict__ Kh, const __half* __restrict__ Kl,
           const __half* __restrict__ Vh, const __half* __restrict__ Vl,
           __half* __restrict__ Oh, float scale)
{
    const int z  = blockIdx.y;            // b*NH + h
    const int bb = z >> 4, hh = z & 15;
    const int q0 = blockIdx.x * 128;
    const int tid = threadIdx.x, lane = tid & 31, w = tid >> 5;
    const int wq = w >> 1, wk = w & 1;
    const int fr = lane >> 2, fc = (lane & 3) * 2;

    const uint32_t smem = smem_u32(sm_raw);

    const __half* Qb  = Qg + (long long)bb * S_ * (NH_ * DQK) + hh * DQK;
    const __half* Khb = Kh + (long long)bb * S_ * (NH_ * DQK) + hh * DQK;
    const __half* Klb = Kl + (long long)bb * S_ * (NH_ * DQK) + hh * DQK;
    const __half* Vhb = Vh + (long long)z * DV_ * S_;
    const __half* Vlb = Vl + (long long)z * DV_ * S_;

    auto load_Q = [&]() {
#pragma unroll
        for (int j = 0; j < 12; j++) {
            int idx = tid + 256 * j;             // 128 rows x 24 chunks
            int r = idx / 24, ch = idx % 24;
            cp16(smem + FL_Q + (uint32_t)(r * 200 + ch * 8) * 2,
                 Qb + (long long)(q0 + r) * (NH_ * DQK) + ch * 8, true);
        }
    };
    auto load_K = [&](int kb, int st) {
        uint32_t base = smem + FL_K + st * FL_KS;
#pragma unroll
        for (int j = 0; j < 6; j++) {
            int idx = tid + 256 * j;             // 64 rows x 24 chunks
            int r = idx / 24, ch = idx % 24;
            long long g = (long long)(kb * 64 + r) * (NH_ * DQK) + ch * 8;
            uint32_t so = (uint32_t)(r * 200 + ch * 8) * 2;
            cp16(base + so,          Khb + g, true);
            cp16(base + FL_KLO + so, Klb + g, true);
        }
    };
    auto load_V = [&](int kb) {
#pragma unroll
        for (int j = 0; j < 4; j++) {
            int idx = tid + 256 * j;             // 128 d x 8 chunks
            int d = idx >> 3, ch = idx & 7;
            long long g = (long long)d * S_ + kb * 64 + ch * 8;
            uint32_t so = (uint32_t)(d * 72 + ch * 8) * 2;
            cp16(smem + FL_V + so,          Vhb + g, true);
            cp16(smem + FL_V + FL_VLO + so, Vlb + g, true);
        }
    };

    // ldmatrix per-lane offsets
    uint32_t aQ[2], aP[2], bK[2], bV[4];
    {
        int r = wq * 32 + (lane & 15);
        int c = (lane >> 4) * 8;
        aQ[0] = (uint32_t)((r * 200 + c) * 2);
        aQ[1] = (uint32_t)(((r + 16) * 200 + c) * 2);
        aP[0] = (uint32_t)((r * 72 + c) * 2);
        aP[1] = (uint32_t)(((r + 16) * 72 + c) * 2);
        int lnB = lane & 7, pHi = lane >> 4, kh = ((lane >> 3) & 1) * 8;
#pragma unroll
        for (int p = 0; p < 2; p++) {
            int n = wk * 32 + (2 * p + pHi) * 8 + lnB;
            bK[p] = (uint32_t)((n * 200 + kh) * 2);
        }
#pragma unroll
        for (int p = 0; p < 4; p++) {
            int n = wk * 64 + (2 * p + pHi) * 8 + lnB;
            bV[p] = (uint32_t)((n * 72 + kh) * 2);
        }
    }

    float acc_o[2][8][4] = {};
    float m_st[4], l_st[4];
#pragma unroll
    for (int i = 0; i < 4; i++) { m_st[i] = -1e30f; l_st[i] = 0.f; }

    float* redm = (float*)(sm_raw + FL_RED);          // [2][128]
    float* reds = (float*)(sm_raw + FL_RED + 1024);   // [2][128]
    int rowi[4];
#pragma unroll
    for (int mt = 0; mt < 2; mt++)
#pragma unroll
        for (int rr = 0; rr < 2; rr++)
            rowi[mt * 2 + rr] = wq * 32 + mt * 16 + rr * 8 + fr;

    // prologue: groups g0 = Q+K0, g1 = V0, g2 = K1
    load_Q(); load_K(0, 0); CP_COMMIT();
    load_V(0);              CP_COMMIT();
    load_K(1, 1);           CP_COMMIT();

    for (int kb = 0; kb < 32; kb++) {
        // ---- wait K_kb (group 2*kb); allowed pending: V_kb, K_{kb+1} ----
        if (kb == 31) { CP_WAIT(1); } else { CP_WAIT(2); }
        __syncthreads();

        // ---- S = scale * Q K^T (K split) ----
        float acc_s[2][4][4] = {};
        const uint32_t kbase = smem + FL_K + (kb & 1) * FL_KS;
#pragma unroll
        for (int ks = 0; ks < 12; ks++) {
            const uint32_t kB = ks * 32;
            uint32_t a[2][4];
            ldsm_x4(a[0], smem + FL_Q + aQ[0] + kB);
            ldsm_x4(a[1], smem + FL_Q + aQ[1] + kB);
#pragma unroll
            for (int p = 0; p < 2; p++) {
                uint32_t bh[4], bl[4];
                ldsm_x4(bh, kbase + bK[p] + kB);
                ldsm_x4(bl, kbase + FL_KLO + bK[p] + kB);
#pragma unroll
                for (int sub = 0; sub < 2; sub++) {
                    const int nt = 2 * p + sub;
#pragma unroll
                    for (int mt = 0; mt < 2; mt++) {
                        mma_fp16(acc_s[mt][nt], a[mt], bh + 2 * sub);
                        mma_fp16(acc_s[mt][nt], a[mt], bl + 2 * sub);
                    }
                }
            }
        }
#pragma unroll
        for (int mt = 0; mt < 2; mt++)
#pragma unroll
            for (int nt = 0; nt < 4; nt++)
#pragma unroll
                for (int c = 0; c < 4; c++) acc_s[mt][nt][c] *= scale;

        // ---- row max ----
#pragma unroll
        for (int sl = 0; sl < 4; sl++) {
            int mt = sl >> 1, rr = sl & 1;
            float v = -1e30f;
#pragma unroll
            for (int nt = 0; nt < 4; nt++) {
                v = fmaxf(v, acc_s[mt][nt][2 * rr]);
                v = fmaxf(v, acc_s[mt][nt][2 * rr + 1]);
            }
            v = fmaxf(v, __shfl_xor_sync(0xffffffffu, v, 1));
            v = fmaxf(v, __shfl_xor_sync(0xffffffffu, v, 2));
            if ((lane & 3) == 0) redm[wk * 128 + rowi[sl]] = v;
        }
        __syncthreads();

        float alpha[4];
#pragma unroll
        for (int sl = 0; sl < 4; sl++) {
            float bm = fmaxf(redm[rowi[sl]], redm[128 + rowi[sl]]);
            float mn = fmaxf(m_st[sl], bm);
            alpha[sl] = __expf(m_st[sl] - mn);
            m_st[sl] = mn;
        }

        // ---- p = exp(s - m), store P fp16, partial row sums ----
#pragma unroll
        for (int sl = 0; sl < 4; sl++) {
            int mt = sl >> 1, rr = sl & 1;
            int prow = rowi[sl];
            float s = 0.f;
#pragma unroll
            for (int nt = 0; nt < 4; nt++) {
                float p0 = __expf(acc_s[mt][nt][2 * rr]     - m_st[sl]);
                float p1 = __expf(acc_s[mt][nt][2 * rr + 1] - m_st[sl]);
                s += p0 + p1;
                *(__half2*)(sm_raw + FL_P + (prow * 72 + wk * 32 + nt * 8 + fc) * 2)
                    = __floats2half2_rn(p0, p1);
            }
            s += __shfl_xor_sync(0xffffffffu, s, 1);
            s += __shfl_xor_sync(0xffffffffu, s, 2);
            if ((lane & 3) == 0) reds[wk * 128 + prow] = s;
        }

        // ---- wait V_kb (group 2*kb+1) + make P/red visible ----
        if (kb == 31) { CP_WAIT(0); } else { CP_WAIT(1); }
        __syncthreads();

#pragma unroll
        for (int sl = 0; sl < 4; sl++)
            l_st[sl] = alpha[sl] * l_st[sl] + reds[rowi[sl]] + reds[128 + rowi[sl]];

        // ---- rescale O ----
#pragma unroll
        for (int mt = 0; mt < 2; mt++)
#pragma unroll
            for (int nt = 0; nt < 8; nt++)
#pragma unroll
                for (int rr = 0; rr < 2; rr++) {
                    float a = alpha[mt * 2 + rr];
                    acc_o[mt][nt][2 * rr]     *= a;
                    acc_o[mt][nt][2 * rr + 1] *= a;
                }

        // ---- O += P V (V split) ----
#pragma unroll
        for (int ks = 0; ks < 4; ks++) {
            const uint32_t kB = ks * 32;
            uint32_t a[2][4];
            ldsm_x4(a[0], smem + FL_P + aP[0] + kB);
            ldsm_x4(a[1], smem + FL_P + aP[1] + kB);
#pragma unroll
            for (int p = 0; p < 4; p++) {
                uint32_t bh[4], bl[4];
                ldsm_x4(bh, smem + FL_V + bV[p] + kB);
                ldsm_x4(bl, smem + FL_V + FL_VLO + bV[p] + kB);
#pragma unroll
                for (int sub = 0; sub < 2; sub++) {
                    const int nt = 2 * p + sub;
#pragma unroll
                    for (int mt = 0; mt < 2; mt++) {
                        mma_fp16(acc_o[mt][nt], a[mt], bh + 2 * sub);
                        mma_fp16(acc_o[mt][nt], a[mt], bl + 2 * sub);
                    }
                }
            }
        }
        __syncthreads();   // all reads of V/P done before refill

        if (kb + 1 < 32) { load_V(kb + 1);            CP_COMMIT(); }
        if (kb + 2 < 32) { load_K(kb + 2, kb & 1);    CP_COMMIT(); }
    }

    // ---- epilogue: O /= l, write fp16 ----
    __half* Ob = Oh + (long long)bb * S_ * (NH_ * DV_) + hh * DV_;
#pragma unroll
    for (int mt = 0; mt < 2; mt++)
#pragma unroll
        for (int rr = 0; rr < 2; rr++) {
            int sl = mt * 2 + rr;
            float inv = 1.f / l_st[sl];
            long long row = q0 + rowi[sl];
#pragma unroll
            for (int nt = 0; nt < 8; nt++) {
                int col = wk * 64 + nt * 8 + fc;
                *(__half2*)(Ob + row * (NH_ * DV_) + col) =
                    __floats2half2_rn(acc_o[mt][nt][2 * rr] * inv,
                                      acc_o[mt][nt][2 * rr + 1] * inv);
            }
        }
}

// ---------------- fp32 -> fp16 (hi only) ----------------
__global__ void convert_h_kernel(const float* __restrict__ x,
                                 __half* __restrict__ h, long long n)
{
    long long i = (long long)blockIdx.x * 256 + threadIdx.x;
    if (i < n) h[i] = __float2half_rn(x[i]);
}

// ---------------- fp32 -> (hi,lo) fp16 convert ----------------
__global__ void convert_split_kernel(const float* __restrict__ x,
                                     __half* __restrict__ h,
                                     __half* __restrict__ l, long long n)
{
    long long i = (long long)blockIdx.x * 256 + threadIdx.x;
    if (i < n) split_write(x[i], h + i, l + i);
}

// ---------------- RMSNorm -> fp16 hi ----------------
__global__ void __launch_bounds__(256)
rmsnorm_h_kernel(const float* __restrict__ x, int ldx, const float* __restrict__ w,
                 __half* __restrict__ yh, int ldy, int cols)
{
    const int row = blockIdx.x;
    const float* xr = x + (long long)row * ldx;
    float ss = 0.f;
    for (int c = threadIdx.x; c < cols; c += 256) { float v = xr[c]; ss += v * v; }
    __shared__ float red[256];
    red[threadIdx.x] = ss;
    __syncthreads();
    for (int s = 128; s > 0; s >>= 1) {
        if (threadIdx.x < s) red[threadIdx.x] += red[threadIdx.x + s];
        __syncthreads();
    }
    float inv = 1.f / sqrtf(red[0] / (float)cols + 1e-6f);
    long long base = (long long)row * ldy;
    for (int c = threadIdx.x; c < cols; c += 256)
        yh[base + c] = __float2half_rn(w[c] * xr[c] * inv);
}

// ---------------- RoPE ----------------
__global__ void freqs_kernel(float* __restrict__ cosd, float* __restrict__ sind)
{
    int t = blockIdx.x, i = threadIdx.x;
    double inv = pow(10000.0, -(double)(2 * i) / (double)DROPE);
    double f = (double)t * inv;
    cosd[t * 32 + i] = (float)cos(f);
    sind[t * 32 + i] = (float)sin(f);
}

__global__ void __launch_bounds__(512)
rope_q_kernel(float* __restrict__ q, const float* __restrict__ cosd,
              const float* __restrict__ sind)
{
    int m = blockIdx.x;
    int t = m & (S_ - 1);
    int h = threadIdx.x >> 5, i = threadIdx.x & 31;
    float cs = cosd[t * 32 + i], sn = sind[t * 32 + i];
    long long base = (long long)m * (NH_ * DQK) + h * DQK + DNOPE + 2 * i;
    float e = q[base], o = q[base + 1];
    q[base]     = e * cs - o * sn;
    q[base + 1] = e * sn + o * cs;
}

__global__ void rope_k_kernel(const float* __restrict__ kv, float* __restrict__ kpe,
                              const float* __restrict__ cosd, const float* __restrict__ sind)
{
    int m = blockIdx.x;
    int t = m & (S_ - 1);
    int i = threadIdx.x;
    float cs = cosd[t * 32 + i], sn = sind[t * 32 + i];
    long long base = (long long)m * (KVLORA + DROPE) + KVLORA + 2 * i;
    float e = kv[base], o = kv[base + 1];
    kpe[m * DROPE + 2 * i]     = e * cs - o * sn;
    kpe[m * DROPE + 2 * i + 1] = e * sn + o * cs;
}

// ---------------- kf assembly (split fp16) ----------------
__global__ void build_kf_kernel(const float* __restrict__ kvx, const float* __restrict__ kpe,
                                __half* __restrict__ kfh, __half* __restrict__ kfl)
{
    long long idx = (long long)blockIdx.x * 256 + threadIdx.x;
    int col = (int)(idx % (NH_ * DQK));
    long long m = idx / (NH_ * DQK);
    int h = col / DQK, d = col % DQK;
    float v;
    if (d < DNOPE) v = kvx[m * (NH_ * (DNOPE + DV_)) + h * (DNOPE + DV_) + d];
    else           v = kpe[m * DROPE + (d - DNOPE)];
    split_write(v, kfh + idx, kfl + idx);
}

// ---------------- V extraction + transpose: vt[b][h][d][s] ----------------
__global__ void __launch_bounds__(256)
transpose_v_kernel(const float* __restrict__ kvx,
                   __half* __restrict__ vth, __half* __restrict__ vtl)
{
    __shared__ float t[32][33];
    int z = blockIdx.z;
    int b = z / NH_, h = z % NH_;
    int s0 = blockIdx.x * 32, d0 = blockIdx.y * 32;
    int tx = threadIdx.x & 31, ty = threadIdx.x >> 5;
#pragma unroll
    for (int i = ty; i < 32; i += 8)
        t[i][tx] = kvx[((long long)(b * S_ + s0 + i)) * (NH_ * (DNOPE + DV_))
                       + h * (DNOPE + DV_) + DNOPE + d0 + tx];
    __syncthreads();
#pragma unroll
    for (int i = ty; i < 32; i += 8) {
        long long o = ((long long)z * DV_ + d0 + i) * S_ + s0 + tx;
        split_write(t[tx][i], vth + o, vtl + o);
    }
}

// ---------------- launch ----------------
extern "C" void kernel_launch(void* const* d_in, const int* in_sizes, int n_in,
                              void* d_out, int out_size)
{
    const float* hs        = (const float*)d_in[0];
    const float* wq_a      = (const float*)d_in[1];
    const float* q_norm_w  = (const float*)d_in[2];
    const float* wq_b      = (const float*)d_in[3];
    const float* wkv_a     = (const float*)d_in[4];
    const float* kv_norm_w = (const float*)d_in[5];
    const float* wkv_b     = (const float*)d_in[6];
    const float* wo        = (const float*)d_in[7];
    float* out = (float*)d_out;

    cudaFuncSetAttribute(hgemm, cudaFuncAttributeMaxDynamicSharedMemorySize, GEMM_SMEM);
    cudaFuncSetAttribute(flash_attn, cudaFuncAttributeMaxDynamicSharedMemorySize, FL_SMEM);

    float *p_qa, *p_q, *p_kv, *p_kpe, *p_kvx, *p_cos, *p_sin;
    cudaGetSymbolAddress((void**)&p_qa,  g_qa);
    cudaGetSymbolAddress((void**)&p_q,   g_q);
    cudaGetSymbolAddress((void**)&p_kv,  g_kv);
    cudaGetSymbolAddress((void**)&p_kpe, g_kpe);
    cudaGetSymbolAddress((void**)&p_kvx, g_kvx);
    cudaGetSymbolAddress((void**)&p_cos, g_cos);
    cudaGetSymbolAddress((void**)&p_sin, g_sin);

    __half *hs_h, *wqa_h, *wqa_l, *wqb_h, *wqb_l, *wkva_h, *wkva_l;
    __half *wkvb_h, *wkvb_l, *wo_h, *wo_l, *qa_h, *q_h;
    __half *kvc_h, *kf_h, *kf_l, *vt_h, *vt_l, *ao_h;
    cudaGetSymbolAddress((void**)&hs_h,  g_hs_h);
    cudaGetSymbolAddress((void**)&wqa_h, g_wqa_h);  cudaGetSymbolAddress((void**)&wqa_l, g_wqa_l);
    cudaGetSymbolAddress((void**)&wqb_h, g_wqb_h);  cudaGetSymbolAddress((void**)&wqb_l, g_wqb_l);
    cudaGetSymbolAddress((void**)&wkva_h, g_wkva_h); cudaGetSymbolAddress((void**)&wkva_l, g_wkva_l);
    cudaGetSymbolAddress((void**)&wkvb_h, g_wkvb_h); cudaGetSymbolAddress((void**)&wkvb_l, g_wkvb_l);
    cudaGetSymbolAddress((void**)&wo_h,  g_wo_h);   cudaGetSymbolAddress((void**)&wo_l,  g_wo_l);
    cudaGetSymbolAddress((void**)&qa_h,  g_qa_h);
    cudaGetSymbolAddress((void**)&q_h,   g_qh);
    cudaGetSymbolAddress((void**)&kvc_h, g_kvc_h);
    cudaGetSymbolAddress((void**)&kf_h,  g_kf_h);   cudaGetSymbolAddress((void**)&kf_l,  g_kf_l);
    cudaGetSymbolAddress((void**)&vt_h,  g_vt_h);   cudaGetSymbolAddress((void**)&vt_l,  g_vt_l);
    cudaGetSymbolAddress((void**)&ao_h,  g_ao_h);

    const float scale = 1.0f / sqrtf((float)DQK);
    auto cvblocks = [](long long n) { return (int)((n + 255) / 256); };
    auto ntiles = [](int n) { return (n + 127) / 128; };

    freqs_kernel<<<S_, 32>>>(p_cos, p_sin);

    convert_h_kernel<<<cvblocks((long long)M_ * H_), 256>>>(hs, hs_h, (long long)M_ * H_);
    convert_split_kernel<<<cvblocks((long long)QLORA * H_), 256>>>(wq_a, wqa_h, wqa_l, (long long)QLORA * H_);
    convert_split_kernel<<<cvblocks((long long)NH_ * DQK * QLORA), 256>>>(wq_b, wqb_h, wqb_l, (long long)NH_ * DQK * QLORA);
    convert_split_kernel<<<cvblocks((long long)(KVLORA + DROPE) * H_), 256>>>(wkv_a, wkva_h, wkva_l, (long long)(KVLORA + DROPE) * H_);
    convert_split_kernel<<<cvblocks((long long)NH_ * (DNOPE + DV_) * KVLORA), 256>>>(wkv_b, wkvb_h, wkvb_l, (long long)NH_ * (DNOPE + DV_) * KVLORA);
    convert_split_kernel<<<cvblocks((long long)H_ * NH_ * DV_), 256>>>(wo, wo_h, wo_l, (long long)H_ * NH_ * DV_);

    // q_a = hs @ wq_a^T   [4096 x 1536] K=2048
    hgemm<<<dim3(ntiles(QLORA), M_ / 128, 1), 256, GEMM_SMEM>>>(
        hs_h, wqa_h, wqa_l, p_qa, QLORA, H_, H_, H_, QLORA,
        0, 0, 0, 0, 0, 0, 1, 1.f);

    rmsnorm_h_kernel<<<M_, 256>>>(p_qa, QLORA, q_norm_w, qa_h, QLORA, QLORA);

    // q = q_a @ wq_b^T    [4096 x 3072] K=1536
    hgemm<<<dim3(ntiles(NH_ * DQK), M_ / 128, 1), 256, GEMM_SMEM>>>(
        qa_h, wqb_h, wqb_l, p_q, NH_ * DQK, QLORA, QLORA, QLORA, NH_ * DQK,
        0, 0, 0, 0, 0, 0, 1, 1.f);

    // kv = hs @ wkv_a^T   [4096 x 576] K=2048
    hgemm<<<dim3(ntiles(KVLORA + DROPE), M_ / 128, 1), 256, GEMM_SMEM>>>(
        hs_h, wkva_h, wkva_l, p_kv, KVLORA + DROPE, H_, H_, H_, KVLORA + DROPE,
        0, 0, 0, 0, 0, 0, 1, 1.f);

    rmsnorm_h_kernel<<<M_, 256>>>(p_kv, KVLORA + DROPE, kv_norm_w, kvc_h, KVLORA, KVLORA);
    rope_k_kernel<<<M_, 32>>>(p_kv, p_kpe, p_cos, p_sin);

    // kv_x = kv_c @ wkv_b^T  [4096 x 4096] K=512
    hgemm<<<dim3(ntiles(NH_ * (DNOPE + DV_)), M_ / 128, 1), 256, GEMM_SMEM>>>(
        kvc_h, wkvb_h, wkvb_l, p_kvx, NH_ * (DNOPE + DV_), KVLORA, KVLORA, KVLORA,
        NH_ * (DNOPE + DV_), 0, 0, 0, 0, 0, 0, 1, 1.f);

    rope_q_kernel<<<M_, 512>>>(p_q, p_cos, p_sin);
    convert_h_kernel<<<cvblocks((long long)M_ * NH_ * DQK), 256>>>(p_q, q_h, (long long)M_ * NH_ * DQK);
    build_kf_kernel<<<cvblocks((long long)M_ * NH_ * DQK), 256>>>(p_kvx, p_kpe, kf_h, kf_l);
    transpose_v_kernel<<<dim3(S_ / 32, DV_ / 32, B_ * NH_), 256>>>(p_kvx, vt_h, vt_l);

    // fused attention: ao_h = softmax(scale * Q Kf^T) V
    flash_attn<<<dim3(S_ / 128, B_ * NH_), 256, FL_SMEM>>>(
        q_h, kf_h, kf_l, vt_h, vt_l, ao_h, scale);

    // out = ao @ wo^T   [4096 x 2048] K=2048
    hgemm<<<dim3(ntiles(H_), M_ / 128, 1), 256, GEMM_SMEM>>>(
        ao_h, wo_h, wo_l, out, H_, NH_ * DV_, NH_ * DV_, NH_ * DV_, H_,
        0, 0, 0, 0, 0, 0, 1, 1.f);
}

// round 12
// speedup vs baseline: 6.9938x; 1.5746x over previous
#include <cuda_runtime.h>
#include <cuda_fp16.h>
#include <math.h>
#include <stdint.h>

// ---------------- problem constants ----------------
#define B_    2
#define S_    2048
#define H_    2048
#define NH_   16
#define QLORA 1536
#define KVLORA 512
#define DNOPE 128
#define DROPE 64
#define DV_   128
#define DQK   192
#define M_    (B_ * S_)    // 4096

// ---------------- fp32 scratch ----------------
__device__ __align__(16) float g_qa  [(size_t)M_ * QLORA];
__device__ __align__(16) float g_q   [(size_t)M_ * (NH_ * DQK)];
__device__ __align__(16) float g_kv  [(size_t)M_ * (KVLORA + DROPE)];
__device__ __align__(16) float g_kpe [(size_t)M_ * DROPE];
__device__ __align__(16) float g_kvx [(size_t)M_ * (NH_ * (DNOPE + DV_))];
__device__ float g_cos [S_ * (DROPE / 2)];
__device__ float g_sin [S_ * (DROPE / 2)];

// ---------------- fp16 operand buffers (all plain fp16 now) ----------------
__device__ __align__(16) __half g_hs_h [(size_t)M_ * H_];
__device__ __align__(16) __half g_wqa_h[(size_t)QLORA * H_];
__device__ __align__(16) __half g_wqb_h[(size_t)NH_ * DQK * QLORA];
__device__ __align__(16) __half g_wkva_h[(size_t)(KVLORA + DROPE) * H_];
__device__ __align__(16) __half g_wkvb_h[(size_t)NH_ * (DNOPE + DV_) * KVLORA];
__device__ __align__(16) __half g_wo_h [(size_t)H_ * NH_ * DV_];
__device__ __align__(16) __half g_qa_h [(size_t)M_ * QLORA];
__device__ __align__(16) __half g_qh   [(size_t)M_ * NH_ * DQK];
__device__ __align__(16) __half g_kvc_h[(size_t)M_ * KVLORA];
__device__ __align__(16) __half g_kf_h [(size_t)M_ * NH_ * DQK];
__device__ __align__(16) __half g_vt_h [(size_t)B_ * NH_ * DV_ * S_];
__device__ __align__(16) __half g_ao_h [(size_t)M_ * NH_ * DV_];

// ---------------- helpers ----------------
__device__ __forceinline__ uint32_t smem_u32(const void* p) {
    uint32_t a;
    asm("{ .reg .u64 t; cvta.to.shared.u64 t, %1; cvt.u32.u64 %0, t; }" : "=r"(a) : "l"(p));
    return a;
}

__device__ __forceinline__ void cp16(uint32_t dst, const void* src, bool pred) {
    int sz = pred ? 16 : 0;
    asm volatile("cp.async.cg.shared.global [%0], [%1], 16, %2;\n"
                 :: "r"(dst), "l"(src), "r"(sz));
}
#define CP_COMMIT()   asm volatile("cp.async.commit_group;\n" ::: "memory")
#define CP_WAIT(n)    asm volatile("cp.async.wait_group %0;\n" :: "n"(n) : "memory")

__device__ __forceinline__ void mma_fp16(float* c, const uint32_t* a, const uint32_t* b) {
    asm volatile(
        "mma.sync.aligned.m16n8k16.row.col.f32.f16.f16.f32 "
        "{%0,%1,%2,%3}, {%4,%5,%6,%7}, {%8,%9}, {%0,%1,%2,%3};\n"
        : "+f"(c[0]), "+f"(c[1]), "+f"(c[2]), "+f"(c[3])
        : "r"(a[0]), "r"(a[1]), "r"(a[2]), "r"(a[3]), "r"(b[0]), "r"(b[1]));
}

__device__ __forceinline__ void ldsm_x4(uint32_t* r, uint32_t addr) {
    asm volatile("ldmatrix.sync.aligned.m8n8.x4.shared.b16 {%0,%1,%2,%3}, [%4];"
        : "=r"(r[0]), "=r"(r[1]), "=r"(r[2]), "=r"(r[3]) : "r"(addr));
}

// ---------------- pipelined fp16 tensor-core GEMM (plain A, plain B) ----------------
// C[m,n] = alpha * sum_k A[m,k] * B[n,k]   (B row-major [n][k], K-contiguous)
// Tile 128x128, K-chunk 32, 3-stage cp.async pipeline, 256 thr, 2 CTA/SM.
#define STG_A   0
#define STG_B   10240
#define STG_BYTES 20480
#define GEMM_SMEM (3 * STG_BYTES)

extern __shared__ char sm_raw[];

__global__ void __launch_bounds__(256, 2)
hgemm(const __half* __restrict__ A,
      const __half* __restrict__ B,
      float* __restrict__ C,
      int N, int K, int lda, int ldb, int ldc,
      long long sAb, long long sAhh, long long sBb, long long sBhh,
      long long sCb, long long sChh, int nh, float alpha)
{
    const int z = blockIdx.z;
    const int bb = z / nh, hh = z % nh;
    A += bb * sAb + hh * sAhh;
    B += bb * sBb + hh * sBhh;
    C += bb * sCb + hh * sChh;

    const int tid = threadIdx.x;
    const int lane = tid & 31, w = tid >> 5;
    const int wm = (w >> 1) * 32, wn = (w & 1) * 64;
    const int m0 = blockIdx.y * 128, n0 = blockIdx.x * 128;
    const int fr = lane >> 2, fc = (lane & 3) * 2;
    const int nk = K >> 5;

    const uint32_t smem = smem_u32(sm_raw);

    uint32_t aoff[2], boff[4];
    {
        int r = wm + (lane & 15);
        int c = (lane >> 4) * 8;
        aoff[0] = (uint32_t)((r * 40 + c) * 2);
        aoff[1] = (uint32_t)(((r + 16) * 40 + c) * 2);
        int lnB = lane & 7;
        int pHi = lane >> 4;
        int kh  = ((lane >> 3) & 1) * 8;
#pragma unroll
        for (int p = 0; p < 4; p++) {
            int n = wn + (2 * p + pHi) * 8 + lnB;
            boff[p] = (uint32_t)((n * 40 + kh) * 2);
        }
    }

    const int lrow0 = tid >> 2, lch = tid & 3;
    const __half* gA  = A + (long long)(m0 + lrow0) * lda + lch * 8;
    const __half* gA2 = gA + 64ll * lda;
    const bool bp1 = (n0 + lrow0) < N;
    const bool bp2 = (n0 + lrow0 + 64) < N;
    const __half* gB  = B + (long long)(n0 + (bp1 ? lrow0 : 0)) * ldb + lch * 8;
    const __half* gB2 = B + (long long)(n0 + (bp2 ? lrow0 + 64 : 0)) * ldb + lch * 8;
    const uint32_t so1 = (uint32_t)(lrow0 * 80 + lch * 16);
    const uint32_t so2 = (uint32_t)((lrow0 + 64) * 80 + lch * 16);

    auto load_stage = [&](int kc, int st) {
        uint32_t sb = smem + st * STG_BYTES;
        cp16(sb + STG_A + so1, gA  + kc, true);
        cp16(sb + STG_A + so2, gA2 + kc, true);
        cp16(sb + STG_B + so1, gB  + kc, bp1);
        cp16(sb + STG_B + so2, gB2 + kc, bp2);
        CP_COMMIT();
    };

    float acc[2][8][4] = {};

    load_stage(0, 0);
    if (nk > 1) load_stage(32, 1); else CP_COMMIT();

    for (int k = 0; k < nk; k++) {
        const int st = k % 3;
        if (k + 2 < nk) load_stage((k + 2) * 32, (k + 2) % 3);
        else CP_COMMIT();
        CP_WAIT(2);
        __syncthreads();

        const uint32_t sb = smem + st * STG_BYTES;

#pragma unroll
        for (int ks = 0; ks < 2; ks++) {
            const uint32_t kB = ks * 32;
            uint32_t a[2][4];
#pragma unroll
            for (int mt = 0; mt < 2; mt++)
                ldsm_x4(a[mt], sb + STG_A + aoff[mt] + kB);
#pragma unroll
            for (int p = 0; p < 4; p++) {
                uint32_t bh[4];
                ldsm_x4(bh, sb + STG_B + boff[p] + kB);
#pragma unroll
                for (int sub = 0; sub < 2; sub++) {
                    const int nt = 2 * p + sub;
#pragma unroll
                    for (int mt = 0; mt < 2; mt++)
                        mma_fp16(acc[mt][nt], a[mt], bh + 2 * sub);
                }
            }
        }
        __syncthreads();
    }

#pragma unroll
    for (int mt = 0; mt < 2; mt++) {
        int row = m0 + wm + mt * 16 + fr;
#pragma unroll
        for (int nt = 0; nt < 8; nt++) {
            int col = n0 + wn + nt * 8 + fc;
            if (col < N) {
                C[(long long)row * ldc + col]           = alpha * acc[mt][nt][0];
                C[(long long)row * ldc + col + 1]       = alpha * acc[mt][nt][1];
                C[(long long)(row + 8) * ldc + col]     = alpha * acc[mt][nt][2];
                C[(long long)(row + 8) * ldc + col + 1] = alpha * acc[mt][nt][3];
            }
        }
    }
}

// ---------------- fused flash attention (plain fp16 K/V) ----------------
// Per CTA: 128 queries of one (b,h). Online softmax over 32 key blocks of 64.
#define FL_Q    0                         // 128*200*2 = 51200
#define FL_K    51200                     // 2 st * 25600 = 51200
#define FL_KS   25600
#define FL_V    102400                    // 128*72*2 = 18432
#define FL_P    120832                    // 18432
#define FL_RED  139264                    // 2048
#define FL_SMEM 141312

__global__ void __launch_bounds__(256, 1)
flash_attn(const __half* __restrict__ Qg,
           const __half* __restrict__ Kh,
           const __half* __restrict__ Vh,
           __half* __restrict__ Oh, float scale)
{
    const int z  = blockIdx.y;            // b*NH + h
    const int bb = z >> 4, hh = z & 15;
    const int q0 = blockIdx.x * 128;
    const int tid = threadIdx.x, lane = tid & 31, w = tid >> 5;
    const int wq = w >> 1, wk = w & 1;
    const int fr = lane >> 2, fc = (lane & 3) * 2;

    const uint32_t smem = smem_u32(sm_raw);

    const __half* Qb  = Qg + (long long)bb * S_ * (NH_ * DQK) + hh * DQK;
    const __half* Khb = Kh + (long long)bb * S_ * (NH_ * DQK) + hh * DQK;
    const __half* Vhb = Vh + (long long)z * DV_ * S_;

    auto load_Q = [&]() {
#pragma unroll
        for (int j = 0; j < 12; j++) {
            int idx = tid + 256 * j;             // 128 rows x 24 chunks
            int r = idx / 24, ch = idx % 24;
            cp16(smem + FL_Q + (uint32_t)(r * 200 + ch * 8) * 2,
                 Qb + (long long)(q0 + r) * (NH_ * DQK) + ch * 8, true);
        }
    };
    auto load_K = [&](int kb, int st) {
        uint32_t base = smem + FL_K + st * FL_KS;
#pragma unroll
        for (int j = 0; j < 6; j++) {
            int idx = tid + 256 * j;             // 64 rows x 24 chunks
            int r = idx / 24, ch = idx % 24;
            cp16(base + (uint32_t)(r * 200 + ch * 8) * 2,
                 Khb + (long long)(kb * 64 + r) * (NH_ * DQK) + ch * 8, true);
        }
    };
    auto load_V = [&](int kb) {
#pragma unroll
        for (int j = 0; j < 4; j++) {
            int idx = tid + 256 * j;             // 128 d x 8 chunks
            int d = idx >> 3, ch = idx & 7;
            cp16(smem + FL_V + (uint32_t)(d * 72 + ch * 8) * 2,
                 Vhb + (long long)d * S_ + kb * 64 + ch * 8, true);
        }
    };

    uint32_t aQ[2], aP[2], bK[2], bV[4];
    {
        int r = wq * 32 + (lane & 15);
        int c = (lane >> 4) * 8;
        aQ[0] = (uint32_t)((r * 200 + c) * 2);
        aQ[1] = (uint32_t)(((r + 16) * 200 + c) * 2);
        aP[0] = (uint32_t)((r * 72 + c) * 2);
        aP[1] = (uint32_t)(((r + 16) * 72 + c) * 2);
        int lnB = lane & 7, pHi = lane >> 4, kh = ((lane >> 3) & 1) * 8;
#pragma unroll
        for (int p = 0; p < 2; p++) {
            int n = wk * 32 + (2 * p + pHi) * 8 + lnB;
            bK[p] = (uint32_t)((n * 200 + kh) * 2);
        }
#pragma unroll
        for (int p = 0; p < 4; p++) {
            int n = wk * 64 + (2 * p + pHi) * 8 + lnB;
            bV[p] = (uint32_t)((n * 72 + kh) * 2);
        }
    }

    float acc_o[2][8][4] = {};
    float m_st[4], l_st[4];
#pragma unroll
    for (int i = 0; i < 4; i++) { m_st[i] = -1e30f; l_st[i] = 0.f; }

    float* redm = (float*)(sm_raw + FL_RED);          // [2][128]
    float* reds = (float*)(sm_raw + FL_RED + 1024);   // [2][128]
    int rowi[4];
#pragma unroll
    for (int mt = 0; mt < 2; mt++)
#pragma unroll
        for (int rr = 0; rr < 2; rr++)
            rowi[mt * 2 + rr] = wq * 32 + mt * 16 + rr * 8 + fr;

    // prologue: g0 = Q+K0, g1 = V0, g2 = K1
    load_Q(); load_K(0, 0); CP_COMMIT();
    load_V(0);              CP_COMMIT();
    load_K(1, 1);           CP_COMMIT();

    for (int kb = 0; kb < 32; kb++) {
        if (kb == 31) { CP_WAIT(1); } else { CP_WAIT(2); }
        __syncthreads();

        // ---- S = scale * Q K^T ----
        float acc_s[2][4][4] = {};
        const uint32_t kbase = smem + FL_K + (kb & 1) * FL_KS;
#pragma unroll
        for (int ks = 0; ks < 12; ks++) {
            const uint32_t kB = ks * 32;
            uint32_t a[2][4];
            ldsm_x4(a[0], smem + FL_Q + aQ[0] + kB);
            ldsm_x4(a[1], smem + FL_Q + aQ[1] + kB);
#pragma unroll
            for (int p = 0; p < 2; p++) {
                uint32_t bh[4];
                ldsm_x4(bh, kbase + bK[p] + kB);
#pragma unroll
                for (int sub = 0; sub < 2; sub++) {
                    const int nt = 2 * p + sub;
#pragma unroll
                    for (int mt = 0; mt < 2; mt++)
                        mma_fp16(acc_s[mt][nt], a[mt], bh + 2 * sub);
                }
            }
        }
#pragma unroll
        for (int mt = 0; mt < 2; mt++)
#pragma unroll
            for (int nt = 0; nt < 4; nt++)
#pragma unroll
                for (int c = 0; c < 4; c++) acc_s[mt][nt][c] *= scale;

        // ---- row max ----
#pragma unroll
        for (int sl = 0; sl < 4; sl++) {
            int mt = sl >> 1, rr = sl & 1;
            float v = -1e30f;
#pragma unroll
            for (int nt = 0; nt < 4; nt++) {
                v = fmaxf(v, acc_s[mt][nt][2 * rr]);
                v = fmaxf(v, acc_s[mt][nt][2 * rr + 1]);
            }
            v = fmaxf(v, __shfl_xor_sync(0xffffffffu, v, 1));
            v = fmaxf(v, __shfl_xor_sync(0xffffffffu, v, 2));
            if ((lane & 3) == 0) redm[wk * 128 + rowi[sl]] = v;
        }
        __syncthreads();

        float alpha[4];
#pragma unroll
        for (int sl = 0; sl < 4; sl++) {
            float bm = fmaxf(redm[rowi[sl]], redm[128 + rowi[sl]]);
            float mn = fmaxf(m_st[sl], bm);
            alpha[sl] = __expf(m_st[sl] - mn);
            m_st[sl] = mn;
        }

        // ---- p = exp(s - m), store P fp16, partial sums ----
#pragma unroll
        for (int sl = 0; sl < 4; sl++) {
            int mt = sl >> 1, rr = sl & 1;
            int prow = rowi[sl];
            float s = 0.f;
#pragma unroll
            for (int nt = 0; nt < 4; nt++) {
                float p0 = __expf(acc_s[mt][nt][2 * rr]     - m_st[sl]);
                float p1 = __expf(acc_s[mt][nt][2 * rr + 1] - m_st[sl]);
                s += p0 + p1;
                *(__half2*)(sm_raw + FL_P + (prow * 72 + wk * 32 + nt * 8 + fc) * 2)
                    = __floats2half2_rn(p0, p1);
            }
            s += __shfl_xor_sync(0xffffffffu, s, 1);
            s += __shfl_xor_sync(0xffffffffu, s, 2);
            if ((lane & 3) == 0) reds[wk * 128 + prow] = s;
        }

        if (kb == 31) { CP_WAIT(0); } else { CP_WAIT(1); }
        __syncthreads();

#pragma unroll
        for (int sl = 0; sl < 4; sl++)
            l_st[sl] = alpha[sl] * l_st[sl] + reds[rowi[sl]] + reds[128 + rowi[sl]];

        // ---- rescale O ----
#pragma unroll
        for (int mt = 0; mt < 2; mt++)
#pragma unroll
            for (int nt = 0; nt < 8; nt++)
#pragma unroll
                for (int rr = 0; rr < 2; rr++) {
                    float a = alpha[mt * 2 + rr];
                    acc_o[mt][nt][2 * rr]     *= a;
                    acc_o[mt][nt][2 * rr + 1] *= a;
                }

        // ---- O += P V ----
#pragma unroll
        for (int ks = 0; ks < 4; ks++) {
            const uint32_t kB = ks * 32;
            uint32_t a[2][4];
            ldsm_x4(a[0], smem + FL_P + aP[0] + kB);
            ldsm_x4(a[1], smem + FL_P + aP[1] + kB);
#pragma unroll
            for (int p = 0; p < 4; p++) {
                uint32_t bh[4];
                ldsm_x4(bh, smem + FL_V + bV[p] + kB);
#pragma unroll
                for (int sub = 0; sub < 2; sub++) {
                    const int nt = 2 * p + sub;
#pragma unroll
                    for (int mt = 0; mt < 2; mt++)
                        mma_fp16(acc_o[mt][nt], a[mt], bh + 2 * sub);
                }
            }
        }
        __syncthreads();

        if (kb + 1 < 32) { load_V(kb + 1);         CP_COMMIT(); }
        if (kb + 2 < 32) { load_K(kb + 2, kb & 1); CP_COMMIT(); }
    }

    // ---- epilogue ----
    __half* Ob = Oh + (long long)bb * S_ * (NH_ * DV_) + hh * DV_;
#pragma unroll
    for (int mt = 0; mt < 2; mt++)
#pragma unroll
        for (int rr = 0; rr < 2; rr++) {
            int sl = mt * 2 + rr;
            float inv = 1.f / l_st[sl];
            long long row = q0 + rowi[sl];
#pragma unroll
            for (int nt = 0; nt < 8; nt++) {
                int col = wk * 64 + nt * 8 + fc;
                *(__half2*)(Ob + row * (NH_ * DV_) + col) =
                    __floats2half2_rn(acc_o[mt][nt][2 * rr] * inv,
                                      acc_o[mt][nt][2 * rr + 1] * inv);
            }
        }
}

// ---------------- fp32 -> fp16 ----------------
__global__ void convert_h_kernel(const float* __restrict__ x,
                                 __half* __restrict__ h, long long n)
{
    long long i = (long long)blockIdx.x * 256 + threadIdx.x;
    if (i < n) h[i] = __float2half_rn(x[i]);
}

// ---------------- RMSNorm -> fp16 ----------------
__global__ void __launch_bounds__(256)
rmsnorm_h_kernel(const float* __restrict__ x, int ldx, const float* __restrict__ w,
                 __half* __restrict__ yh, int ldy, int cols)
{
    const int row = blockIdx.x;
    const float* xr = x + (long long)row * ldx;
    float ss = 0.f;
    for (int c = threadIdx.x; c < cols; c += 256) { float v = xr[c]; ss += v * v; }
    __shared__ float red[256];
    red[threadIdx.x] = ss;
    __syncthreads();
    for (int s = 128; s > 0; s >>= 1) {
        if (threadIdx.x < s) red[threadIdx.x] += red[threadIdx.x + s];
        __syncthreads();
    }
    float inv = 1.f / sqrtf(red[0] / (float)cols + 1e-6f);
    long long base = (long long)row * ldy;
    for (int c = threadIdx.x; c < cols; c += 256)
        yh[base + c] = __float2half_rn(w[c] * xr[c] * inv);
}

// ---------------- RoPE ----------------
__global__ void freqs_kernel(float* __restrict__ cosd, float* __restrict__ sind)
{
    int t = blockIdx.x, i = threadIdx.x;
    double inv = pow(10000.0, -(double)(2 * i) / (double)DROPE);
    double f = (double)t * inv;
    cosd[t * 32 + i] = (float)cos(f);
    sind[t * 32 + i] = (float)sin(f);
}

// fused: rope on q_pe dims + fp16 convert of full q row -> q_h
__global__ void __launch_bounds__(256)
rope_q_convert_kernel(const float* __restrict__ q, __half* __restrict__ qh,
                      const float* __restrict__ cosd, const float* __restrict__ sind)
{
    int m = blockIdx.x;
    int t = m & (S_ - 1);
    long long base = (long long)m * (NH_ * DQK);
#pragma unroll
    for (int j = 0; j < 6; j++) {
        int pr = threadIdx.x + 256 * j;          // pair index < 1536
        int col = 2 * pr;
        int d = col % DQK;
        float e = q[base + col], o = q[base + col + 1];
        if (d >= DNOPE) {
            int i = (d - DNOPE) >> 1;
            float cs = cosd[t * 32 + i], sn = sind[t * 32 + i];
            float re = e * cs - o * sn;
            float im = e * sn + o * cs;
            e = re; o = im;
        }
        *(__half2*)(qh + base + col) = __floats2half2_rn(e, o);
    }
}

__global__ void rope_k_kernel(const float* __restrict__ kv, float* __restrict__ kpe,
                              const float* __restrict__ cosd, const float* __restrict__ sind)
{
    int m = blockIdx.x;
    int t = m & (S_ - 1);
    int i = threadIdx.x;
    float cs = cosd[t * 32 + i], sn = sind[t * 32 + i];
    long long base = (long long)m * (KVLORA + DROPE) + KVLORA + 2 * i;
    float e = kv[base], o = kv[base + 1];
    kpe[m * DROPE + 2 * i]     = e * cs - o * sn;
    kpe[m * DROPE + 2 * i + 1] = e * sn + o * cs;
}

// ---------------- kf assembly (fp16) ----------------
__global__ void build_kf_kernel(const float* __restrict__ kvx, const float* __restrict__ kpe,
                                __half* __restrict__ kfh)
{
    long long idx = (long long)blockIdx.x * 256 + threadIdx.x;
    int col = (int)(idx % (NH_ * DQK));
    long long m = idx / (NH_ * DQK);
    int h = col / DQK, d = col % DQK;
    float v;
    if (d < DNOPE) v = kvx[m * (NH_ * (DNOPE + DV_)) + h * (DNOPE + DV_) + d];
    else           v = kpe[m * DROPE + (d - DNOPE)];
    kfh[idx] = __float2half_rn(v);
}

// ---------------- V extraction + transpose: vt[b][h][d][s] ----------------
__global__ void __launch_bounds__(256)
transpose_v_kernel(const float* __restrict__ kvx, __half* __restrict__ vth)
{
    __shared__ float t[32][33];
    int z = blockIdx.z;
    int b = z / NH_, h = z % NH_;
    int s0 = blockIdx.x * 32, d0 = blockIdx.y * 32;
    int tx = threadIdx.x & 31, ty = threadIdx.x >> 5;
#pragma unroll
    for (int i = ty; i < 32; i += 8)
        t[i][tx] = kvx[((long long)(b * S_ + s0 + i)) * (NH_ * (DNOPE + DV_))
                       + h * (DNOPE + DV_) + DNOPE + d0 + tx];
    __syncthreads();
#pragma unroll
    for (int i = ty; i < 32; i += 8) {
        long long o = ((long long)z * DV_ + d0 + i) * S_ + s0 + tx;
        vth[o] = __float2half_rn(t[tx][i]);
    }
}

// ---------------- launch ----------------
extern "C" void kernel_launch(void* const* d_in, const int* in_sizes, int n_in,
                              void* d_out, int out_size)
{
    const float* hs        = (const float*)d_in[0];
    const float* wq_a      = (const float*)d_in[1];
    const float* q_norm_w  = (const float*)d_in[2];
    const float* wq_b      = (const float*)d_in[3];
    const float* wkv_a     = (const float*)d_in[4];
    const float* kv_norm_w = (const float*)d_in[5];
    const float* wkv_b     = (const float*)d_in[6];
    const float* wo        = (const float*)d_in[7];
    float* out = (float*)d_out;

    cudaFuncSetAttribute(hgemm, cudaFuncAttributeMaxDynamicSharedMemorySize, GEMM_SMEM);
    cudaFuncSetAttribute(flash_attn, cudaFuncAttributeMaxDynamicSharedMemorySize, FL_SMEM);

    float *p_qa, *p_q, *p_kv, *p_kpe, *p_kvx, *p_cos, *p_sin;
    cudaGetSymbolAddress((void**)&p_qa,  g_qa);
    cudaGetSymbolAddress((void**)&p_q,   g_q);
    cudaGetSymbolAddress((void**)&p_kv,  g_kv);
    cudaGetSymbolAddress((void**)&p_kpe, g_kpe);
    cudaGetSymbolAddress((void**)&p_kvx, g_kvx);
    cudaGetSymbolAddress((void**)&p_cos, g_cos);
    cudaGetSymbolAddress((void**)&p_sin, g_sin);

    __half *hs_h, *wqa_h, *wqb_h, *wkva_h, *wkvb_h, *wo_h, *qa_h, *q_h;
    __half *kvc_h, *kf_h, *vt_h, *ao_h;
    cudaGetSymbolAddress((void**)&hs_h,  g_hs_h);
    cudaGetSymbolAddress((void**)&wqa_h, g_wqa_h);
    cudaGetSymbolAddress((void**)&wqb_h, g_wqb_h);
    cudaGetSymbolAddress((void**)&wkva_h, g_wkva_h);
    cudaGetSymbolAddress((void**)&wkvb_h, g_wkvb_h);
    cudaGetSymbolAddress((void**)&wo_h,  g_wo_h);
    cudaGetSymbolAddress((void**)&qa_h,  g_qa_h);
    cudaGetSymbolAddress((void**)&q_h,   g_qh);
    cudaGetSymbolAddress((void**)&kvc_h, g_kvc_h);
    cudaGetSymbolAddress((void**)&kf_h,  g_kf_h);
    cudaGetSymbolAddress((void**)&vt_h,  g_vt_h);
    cudaGetSymbolAddress((void**)&ao_h,  g_ao_h);

    const float scale = 1.0f / sqrtf((float)DQK);
    auto cvblocks = [](long long n) { return (int)((n + 255) / 256); };
    auto ntiles = [](int n) { return (n + 127) / 128; };

    freqs_kernel<<<S_, 32>>>(p_cos, p_sin);

    convert_h_kernel<<<cvblocks((long long)M_ * H_), 256>>>(hs, hs_h, (long long)M_ * H_);
    convert_h_kernel<<<cvblocks((long long)QLORA * H_), 256>>>(wq_a, wqa_h, (long long)QLORA * H_);
    convert_h_kernel<<<cvblocks((long long)NH_ * DQK * QLORA), 256>>>(wq_b, wqb_h, (long long)NH_ * DQK * QLORA);
    convert_h_kernel<<<cvblocks((long long)(KVLORA + DROPE) * H_), 256>>>(wkv_a, wkva_h, (long long)(KVLORA + DROPE) * H_);
    convert_h_kernel<<<cvblocks((long long)NH_ * (DNOPE + DV_) * KVLORA), 256>>>(wkv_b, wkvb_h, (long long)NH_ * (DNOPE + DV_) * KVLORA);
    convert_h_kernel<<<cvblocks((long long)H_ * NH_ * DV_), 256>>>(wo, wo_h, (long long)H_ * NH_ * DV_);

    // q_a = hs @ wq_a^T   [4096 x 1536] K=2048
    hgemm<<<dim3(ntiles(QLORA), M_ / 128, 1), 256, GEMM_SMEM>>>(
        hs_h, wqa_h, p_qa, QLORA, H_, H_, H_, QLORA,
        0, 0, 0, 0, 0, 0, 1, 1.f);

    rmsnorm_h_kernel<<<M_, 256>>>(p_qa, QLORA, q_norm_w, qa_h, QLORA, QLORA);

    // q = q_a @ wq_b^T    [4096 x 3072] K=1536
    hgemm<<<dim3(ntiles(NH_ * DQK), M_ / 128, 1), 256, GEMM_SMEM>>>(
        qa_h, wqb_h, p_q, NH_ * DQK, QLORA, QLORA, QLORA, NH_ * DQK,
        0, 0, 0, 0, 0, 0, 1, 1.f);

    // kv = hs @ wkv_a^T   [4096 x 576] K=2048
    hgemm<<<dim3(ntiles(KVLORA + DROPE), M_ / 128, 1), 256, GEMM_SMEM>>>(
        hs_h, wkva_h, p_kv, KVLORA + DROPE, H_, H_, H_, KVLORA + DROPE,
        0, 0, 0, 0, 0, 0, 1, 1.f);

    rmsnorm_h_kernel<<<M_, 256>>>(p_kv, KVLORA + DROPE, kv_norm_w, kvc_h, KVLORA, KVLORA);
    rope_k_kernel<<<M_, 32>>>(p_kv, p_kpe, p_cos, p_sin);

    // kv_x = kv_c @ wkv_b^T  [4096 x 4096] K=512
    hgemm<<<dim3(ntiles(NH_ * (DNOPE + DV_)), M_ / 128, 1), 256, GEMM_SMEM>>>(
        kvc_h, wkvb_h, p_kvx, NH_ * (DNOPE + DV_), KVLORA, KVLORA, KVLORA,
        NH_ * (DNOPE + DV_), 0, 0, 0, 0, 0, 0, 1, 1.f);

    rope_q_convert_kernel<<<M_, 256>>>(p_q, q_h, p_cos, p_sin);
    build_kf_kernel<<<cvblocks((long long)M_ * NH_ * DQK), 256>>>(p_kvx, p_kpe, kf_h);
    transpose_v_kernel<<<dim3(S_ / 32, DV_ / 32, B_ * NH_), 256>>>(p_kvx, vt_h);

    // fused attention: ao_h = softmax(scale * Q Kf^T) V
    flash_attn<<<dim3(S_ / 128, B_ * NH_), 256, FL_SMEM>>>(
        q_h, kf_h, vt_h, ao_h, scale);

    // out = ao @ wo^T   [4096 x 2048] K=2048
    hgemm<<<dim3(ntiles(H_), M_ / 128, 1), 256, GEMM_SMEM>>>(
        ao_h, wo_h, out, H_, NH_ * DV_, NH_ * DV_, NH_ * DV_, H_,
        0, 0, 0, 0, 0, 0, 1, 1.f);
}